// round 3
// baseline (speedup 1.0000x reference)
#include <cuda_runtime.h>
#include <cuda_bf16.h>

#define Bn  4
#define Tn  2048
#define DMn 768
#define Hn  12
#define DHn 64

// Scratch (device globals — no allocation allowed in kernel_launch)
__device__ __align__(16) float g_q[Bn*Hn*Tn*DHn];
__device__ __align__(16) float g_k[Bn*Hn*Tn*DHn];
__device__ __align__(16) float g_v[Bn*Hn*Tn*DHn];
__device__ __align__(16) float g_o[Bn*Tn*DMn];

// ---------------------------------------------------------------------------
// 128x128x16 SGEMM core, 256 threads, 8x8 micro-tile (2x 4-wide halves at
// stride 64), double-buffered smem. C[m,n] = sum_k A[m,k] * W[n,k].
// ---------------------------------------------------------------------------
#define GEMM_PROLOGUE()                                                        \
    __shared__ float Xs[2][16][128];                                           \
    __shared__ float Ws[2][16][128];                                           \
    const int tid = threadIdx.x;                                               \
    const int lr = tid >> 2, lc = tid & 3;                                     \
    const int tx = tid & 15, ty = tid >> 4;                                    \
    float acc[8][8];                                                           \
    _Pragma("unroll")                                                          \
    for (int i = 0; i < 8; i++)                                                \
        _Pragma("unroll")                                                      \
        for (int j = 0; j < 8; j++) acc[i][j] = 0.f;

#define GEMM_LOAD(k0)                                                          \
    xa0 = *(const float4*)(xbase + (size_t)(k0));                              \
    xa1 = *(const float4*)(xbase + 64 * DMn + (k0));                           \
    wa0 = *(const float4*)(wbase + (size_t)(k0));                              \
    wa1 = *(const float4*)(wbase + 64 * DMn + (k0));

#define GEMM_STORE(bufi)                                                       \
    Xs[bufi][lc*4+0][lr] = xa0.x; Xs[bufi][lc*4+1][lr] = xa0.y;                \
    Xs[bufi][lc*4+2][lr] = xa0.z; Xs[bufi][lc*4+3][lr] = xa0.w;                \
    Xs[bufi][lc*4+0][lr+64] = xa1.x; Xs[bufi][lc*4+1][lr+64] = xa1.y;          \
    Xs[bufi][lc*4+2][lr+64] = xa1.z; Xs[bufi][lc*4+3][lr+64] = xa1.w;          \
    Ws[bufi][lc*4+0][lr] = wa0.x; Ws[bufi][lc*4+1][lr] = wa0.y;                \
    Ws[bufi][lc*4+2][lr] = wa0.z; Ws[bufi][lc*4+3][lr] = wa0.w;                \
    Ws[bufi][lc*4+0][lr+64] = wa1.x; Ws[bufi][lc*4+1][lr+64] = wa1.y;          \
    Ws[bufi][lc*4+2][lr+64] = wa1.z; Ws[bufi][lc*4+3][lr+64] = wa1.w;

#define GEMM_COMPUTE(bufi)                                                     \
    _Pragma("unroll")                                                          \
    for (int kk = 0; kk < 16; kk++) {                                          \
        float4 a0 = *(const float4*)&Xs[bufi][kk][ty*4];                       \
        float4 a1 = *(const float4*)&Xs[bufi][kk][64 + ty*4];                  \
        float4 b0 = *(const float4*)&Ws[bufi][kk][tx*4];                       \
        float4 b1 = *(const float4*)&Ws[bufi][kk][64 + tx*4];                  \
        float a[8] = {a0.x,a0.y,a0.z,a0.w,a1.x,a1.y,a1.z,a1.w};                \
        float b[8] = {b0.x,b0.y,b0.z,b0.w,b1.x,b1.y,b1.z,b1.w};                \
        _Pragma("unroll")                                                      \
        for (int i = 0; i < 8; i++)                                            \
            _Pragma("unroll")                                                  \
            for (int j = 0; j < 8; j++) acc[i][j] += a[i] * b[j];              \
    }

#define GEMM_MAINLOOP()                                                        \
    float4 xa0, xa1, wa0, wa1;                                                 \
    GEMM_LOAD(0);                                                              \
    GEMM_STORE(0);                                                             \
    __syncthreads();                                                           \
    int buf = 0;                                                               \
    for (int kt = 1; kt <= DMn / 16; kt++) {                                   \
        if (kt < DMn / 16) { GEMM_LOAD(kt * 16); }                             \
        GEMM_COMPUTE(buf);                                                     \
        if (kt < DMn / 16) { GEMM_STORE(buf ^ 1); }                            \
        buf ^= 1;                                                              \
        __syncthreads();                                                       \
    }

// ---------------------------------------------------------------------------
// Kernel A: QKV GEMM with fused RoPE + transpose-to-[B,H,T,DH] epilogue.
// blockIdx.x = mat*6 + ntile (mat: 0=Q,1=K,2=V), blockIdx.y = mtile.
// BN=128 spans 2 heads; thread's 4-wide col strips are rope-pair aligned.
// ---------------------------------------------------------------------------
__global__ __launch_bounds__(256) void qkv_gemm(
    const float* __restrict__ x,
    const float* __restrict__ wq, const float* __restrict__ wk,
    const float* __restrict__ wv,
    const float* __restrict__ cosb, const float* __restrict__ sinb)
{
    GEMM_PROLOGUE();
    const int mat = blockIdx.x / 6;
    const int nt  = blockIdx.x % 6;
    const int mt  = blockIdx.y;
    const int m0 = mt * 128, n0 = nt * 128;
    const float* W = (mat == 0) ? wq : ((mat == 1) ? wk : wv);
    const float* xbase = x + (size_t)(m0 + lr) * DMn + lc * 4;
    const float* wbase = W + (size_t)(n0 + lr) * DMn + lc * 4;

    GEMM_MAINLOOP();

    float* dst = (mat == 0) ? g_q : ((mat == 1) ? g_k : g_v);
    const int pi = tx * 2;  // rope pair base for d = tx*4 .. tx*4+3
    #pragma unroll
    for (int r = 0; r < 8; r++) {
        int m = m0 + ((r < 4) ? (ty * 4 + r) : (64 + ty * 4 + r - 4));
        int b = m / Tn, t = m % Tn;
        float c0 = 0.f, s0 = 0.f, c1 = 0.f, s1 = 0.f;
        if (mat < 2) {
            c0 = cosb[t*32 + pi];     s0 = sinb[t*32 + pi];
            c1 = cosb[t*32 + pi + 1]; s1 = sinb[t*32 + pi + 1];
        }
        #pragma unroll
        for (int hn = 0; hn < 2; hn++) {
            int head = nt * 2 + hn;
            float v0 = acc[r][hn*4+0], v1 = acc[r][hn*4+1];
            float v2 = acc[r][hn*4+2], v3 = acc[r][hn*4+3];
            float4 o;
            if (mat < 2) {
                o.x = v0*c0 - v1*s0; o.y = v0*s0 + v1*c0;
                o.z = v2*c1 - v3*s1; o.w = v2*s1 + v3*c1;
            } else {
                o = make_float4(v0, v1, v2, v3);
            }
            *(float4*)(dst + ((size_t)(b*Hn + head)*Tn + t)*DHn + tx*4) = o;
        }
    }
}

// ---------------------------------------------------------------------------
// Kernel B: causal flash attention, fp32. 1 query per thread, 128 q/block,
// 32-key tiles staged in smem (broadcast LDS reads), online softmax.
// grid: (16 qtiles, 48 bh). qtiles processed in reverse for load balance.
// ---------------------------------------------------------------------------
__global__ __launch_bounds__(128) void attn_kernel()
{
    __shared__ __align__(16) float Ks[32 * 64];
    __shared__ __align__(16) float Vs[32 * 64];

    const int qt  = (int)gridDim.x - 1 - (int)blockIdx.x;
    const int bh  = blockIdx.y;
    const int tid = threadIdx.x;
    const int t   = qt * 128 + tid;

    const float* qp = g_q + (bh * Tn + t) * DHn;
    float4 qv[16];
    #pragma unroll
    for (int i = 0; i < 16; i++) qv[i] = *(const float4*)(qp + i * 4);

    float4 av[16];
    #pragma unroll
    for (int i = 0; i < 16; i++) av[i] = make_float4(0.f, 0.f, 0.f, 0.f);

    float mx = -1e30f, l = 0.f;
    const float4* kb = (const float4*)(g_k + bh * Tn * DHn);
    const float4* vb = (const float4*)(g_v + bh * Tn * DHn);
    const int ktmax = 4 * qt + 3;
    float s[32];

    for (int kt = 0; kt <= ktmax; kt++) {
        #pragma unroll
        for (int i = 0; i < 4; i++) {
            ((float4*)Ks)[tid + i * 128] = kb[kt * 512 + tid + i * 128];
            ((float4*)Vs)[tid + i * 128] = vb[kt * 512 + tid + i * 128];
        }
        __syncthreads();

        float mtile = -1e30f;
        #pragma unroll 4
        for (int j = 0; j < 32; j++) {
            const float4* kr = (const float4*)(Ks + j * 64);
            float acc = 0.f;
            #pragma unroll
            for (int d = 0; d < 16; d++) {
                float4 k4 = kr[d];
                acc += qv[d].x * k4.x + qv[d].y * k4.y
                     + qv[d].z * k4.z + qv[d].w * k4.w;
            }
            acc *= 0.125f;
            if (kt * 32 + j > t) acc = -1e30f;
            s[j] = acc;
            mtile = fmaxf(mtile, acc);
        }

        float newm = fmaxf(mx, mtile);
        float corr = __expf(mx - newm);
        mx = newm;
        l *= corr;
        #pragma unroll
        for (int d = 0; d < 16; d++) {
            av[d].x *= corr; av[d].y *= corr; av[d].z *= corr; av[d].w *= corr;
        }

        #pragma unroll 4
        for (int j = 0; j < 32; j++) {
            float p = __expf(s[j] - mx);
            l += p;
            const float4* vr = (const float4*)(Vs + j * 64);
            #pragma unroll
            for (int d = 0; d < 16; d++) {
                float4 v4 = vr[d];
                av[d].x += p * v4.x; av[d].y += p * v4.y;
                av[d].z += p * v4.z; av[d].w += p * v4.w;
            }
        }
        __syncthreads();
    }

    float inv = 1.f / l;
    int b = bh / Hn, h = bh % Hn;
    float* op = g_o + (b * Tn + t) * DMn + h * DHn;
    #pragma unroll
    for (int d = 0; d < 16; d++) {
        *(float4*)(op + d * 4) =
            make_float4(av[d].x * inv, av[d].y * inv, av[d].z * inv, av[d].w * inv);
    }
}

// ---------------------------------------------------------------------------
// Kernel C: output projection out[m,n] = sum_k g_o[m,k] * wo[n,k]
// ---------------------------------------------------------------------------
__global__ __launch_bounds__(256) void proj_gemm(
    const float* __restrict__ wo, float* __restrict__ out)
{
    GEMM_PROLOGUE();
    const int nt = blockIdx.x;
    const int mt = blockIdx.y;
    const int m0 = mt * 128, n0 = nt * 128;
    const float* xbase = g_o + (size_t)(m0 + lr) * DMn + lc * 4;
    const float* wbase = wo  + (size_t)(n0 + lr) * DMn + lc * 4;

    GEMM_MAINLOOP();

    #pragma unroll
    for (int r = 0; r < 8; r++) {
        int m = m0 + ((r < 4) ? (ty * 4 + r) : (64 + ty * 4 + r - 4));
        #pragma unroll
        for (int hn = 0; hn < 2; hn++) {
            *(float4*)(out + (size_t)m * DMn + n0 + hn * 64 + tx * 4) =
                make_float4(acc[r][hn*4+0], acc[r][hn*4+1],
                            acc[r][hn*4+2], acc[r][hn*4+3]);
        }
    }
}

// ---------------------------------------------------------------------------
extern "C" void kernel_launch(void* const* d_in, const int* in_sizes, int n_in,
                              void* d_out, int out_size)
{
    const float* x    = (const float*)d_in[0];
    const float* cosb = (const float*)d_in[1];
    const float* sinb = (const float*)d_in[2];
    const float* wq   = (const float*)d_in[3];
    const float* wk   = (const float*)d_in[4];
    const float* wv   = (const float*)d_in[5];
    const float* wo   = (const float*)d_in[6];
    float* out = (float*)d_out;

    dim3 gA(18, 64);    // 3 mats x 6 ntiles, 64 mtiles
    qkv_gemm<<<gA, 256>>>(x, wq, wk, wv, cosb, sinb);

    dim3 gB(16, 48);    // 16 qtiles, B*H
    attn_kernel<<<gB, 128>>>();

    dim3 gC(6, 64);
    proj_gemm<<<gC, 256>>>(wo, out);
}

// round 5
// speedup vs baseline: 1.9236x; 1.9236x over previous
#include <cuda_runtime.h>
#include <cuda_bf16.h>
#include <cstdint>

#define Bn  4
#define Tn  2048
#define DMn 768
#define Hn  12
#define DHn 64

// Scratch (device globals — no allocation allowed in kernel_launch)
__device__ __align__(16) float g_q[Bn*Hn*Tn*DHn];
__device__ __align__(16) float g_k[Bn*Hn*Tn*DHn];
__device__ __align__(16) float g_v[Bn*Hn*Tn*DHn];
__device__ __align__(16) float g_o[Bn*Tn*DMn];

// ===========================================================================
// HMMA (mma.sync) split-bf16 GEMM machinery.
// C[m,n] = sum_k A[m,k]*B[n,k] with A,B fp32 -> (hi,lo) bf16 decomposition:
// C ≈ Ah·Bh + Al·Bh + Ah·Bl   (lo·lo dropped, ~2^-16 relative)
// Tiles: 128x128 C-block, BK=32, 8 warps (mw 0..3, nw 0..1), warp = 32x64.
// smem per buffer: Ah, Al, Bh, Bl tiles of 128 rows x 64B (8KB each) = 32KB.
// Swizzle: 16B chunk index ^= (row>>1)&3  (conflict-free ldmatrix + STS).
// ===========================================================================

#define OFF_AH 0
#define OFF_AL 8192
#define OFF_BH 16384
#define OFF_BL 24576
#define BUFSZ  32768

__device__ __forceinline__ uint32_t smem_u32(const void* p) {
    uint32_t a;
    asm("{ .reg .u64 t; cvta.to.shared.u64 t, %1; cvt.u32.u64 %0, t; }"
        : "=r"(a) : "l"(p));
    return a;
}

#define SWZ(row, chunk) \
    ((uint32_t)((row) * 64 + ((((chunk) ^ (((row) >> 1) & 3)) & 3) * 16)))

__device__ __forceinline__ void packhl(float x0, float x1,
                                       uint32_t& h, uint32_t& l) {
    __nv_bfloat16 h0 = __float2bfloat16(x0), h1 = __float2bfloat16(x1);
    float r0 = x0 - __bfloat162float(h0), r1 = x1 - __bfloat162float(h1);
    __nv_bfloat16 l0 = __float2bfloat16(r0), l1 = __float2bfloat16(r1);
    h = (uint32_t)__bfloat16_as_ushort(h0) |
        ((uint32_t)__bfloat16_as_ushort(h1) << 16);
    l = (uint32_t)__bfloat16_as_ushort(l0) |
        ((uint32_t)__bfloat16_as_ushort(l1) << 16);
}

#define STS4(addr, r0, r1, r2, r3) \
    asm volatile("st.shared.v4.b32 [%0], {%1, %2, %3, %4};" \
        :: "r"(addr), "r"(r0), "r"(r1), "r"(r2), "r"(r3) : "memory")

#define LDSM4(r, addr) \
    asm volatile("ldmatrix.sync.aligned.m8n8.x4.shared.b16 {%0,%1,%2,%3}, [%4];" \
        : "=r"((r)[0]), "=r"((r)[1]), "=r"((r)[2]), "=r"((r)[3]) : "r"(addr))

#define MMA1(cc, a, b0r, b1r) \
    asm volatile("mma.sync.aligned.m16n8k16.row.col.f32.bf16.bf16.f32 " \
        "{%0,%1,%2,%3}, {%4,%5,%6,%7}, {%8,%9}, {%0,%1,%2,%3};" \
        : "+f"((cc)[0]), "+f"((cc)[1]), "+f"((cc)[2]), "+f"((cc)[3]) \
        : "r"((a)[0]), "r"((a)[1]), "r"((a)[2]), "r"((a)[3]), \
          "r"(b0r), "r"(b1r))

#define MMA_ALL(AF, BF) \
    _Pragma("unroll") \
    for (int mt = 0; mt < 2; mt++) \
        _Pragma("unroll") \
        for (int nt = 0; nt < 8; nt++) \
            MMA1(c[mt][nt], (AF)[mt], (BF)[nt >> 1][(nt & 1) * 2], \
                 (BF)[nt >> 1][(nt & 1) * 2 + 1]);

// one k16 step: hi*hi + lo*hi + hi*lo
#define COMP_KB(kb, SBASE) do {                                               \
    uint32_t aF[2][4], bF[4][4], aT[2][4], bT[4][4];                          \
    _Pragma("unroll")                                                         \
    for (int mt = 0; mt < 2; mt++)                                            \
        LDSM4(aF[mt], (SBASE) + OFF_AH +                                      \
              SWZ(mw * 32 + mt * 16 + a_r, (kb) * 2 + a_cb));                 \
    _Pragma("unroll")                                                         \
    for (int np = 0; np < 4; np++)                                            \
        LDSM4(bF[np], (SBASE) + OFF_BH +                                      \
              SWZ(nw * 64 + np * 16 + b_off, (kb) * 2 + b_cb));               \
    MMA_ALL(aF, bF);                                                          \
    _Pragma("unroll")                                                         \
    for (int mt = 0; mt < 2; mt++)                                            \
        LDSM4(aT[mt], (SBASE) + OFF_AL +                                      \
              SWZ(mw * 32 + mt * 16 + a_r, (kb) * 2 + a_cb));                 \
    MMA_ALL(aT, bF);                                                          \
    _Pragma("unroll")                                                         \
    for (int np = 0; np < 4; np++)                                            \
        LDSM4(bT[np], (SBASE) + OFF_BL +                                      \
              SWZ(nw * 64 + np * 16 + b_off, (kb) * 2 + b_cb));               \
    MMA_ALL(aF, bT);                                                          \
} while (0)

#define GEMM_SETUP()                                                          \
    extern __shared__ unsigned char dynsm[];                                  \
    const uint32_t sbase = smem_u32(dynsm);                                   \
    const int tid = threadIdx.x, lane = tid & 31, wid = tid >> 5;             \
    const int mw = wid & 3, nw = wid >> 2;                                    \
    const int a_r = lane & 15, a_cb = lane >> 4;                              \
    const int b_off = ((lane >> 4) << 3) + (lane & 7), b_cb = (lane >> 3) & 1;\
    const int ldrow = tid >> 1, ldhalf = tid & 1;                             \
    float c[2][8][4];                                                         \
    _Pragma("unroll")                                                         \
    for (int i = 0; i < 2; i++)                                               \
        _Pragma("unroll")                                                     \
        for (int j = 0; j < 8; j++)                                           \
            _Pragma("unroll")                                                 \
            for (int q = 0; q < 4; q++) c[i][j][q] = 0.f;

#define GEMM_LDG(s)                                                           \
    {                                                                         \
        const float4* pa = (const float4*)(gA + (size_t)ldrow * DMn +         \
                                           (s) * 32 + ldhalf * 16);           \
        const float4* pb = (const float4*)(gB + (size_t)ldrow * DMn +         \
                                           (s) * 32 + ldhalf * 16);           \
        ra[0] = pa[0]; ra[1] = pa[1]; ra[2] = pa[2]; ra[3] = pa[3];           \
        rb[0] = pb[0]; rb[1] = pb[1]; rb[2] = pb[2]; rb[3] = pb[3];           \
    }

#define GEMM_STS(bb)                                                          \
    {                                                                         \
        uint32_t h[8], l[8];                                                  \
        _Pragma("unroll")                                                     \
        for (int i = 0; i < 4; i++) {                                         \
            packhl(ra[i].x, ra[i].y, h[i * 2],     l[i * 2]);                 \
            packhl(ra[i].z, ra[i].w, h[i * 2 + 1], l[i * 2 + 1]);             \
        }                                                                     \
        uint32_t o0 = SWZ(ldrow, ldhalf * 2), o1 = SWZ(ldrow, ldhalf * 2 + 1);\
        STS4((bb) + OFF_AH + o0, h[0], h[1], h[2], h[3]);                     \
        STS4((bb) + OFF_AH + o1, h[4], h[5], h[6], h[7]);                     \
        STS4((bb) + OFF_AL + o0, l[0], l[1], l[2], l[3]);                     \
        STS4((bb) + OFF_AL + o1, l[4], l[5], l[6], l[7]);                     \
        _Pragma("unroll")                                                     \
        for (int i = 0; i < 4; i++) {                                         \
            packhl(rb[i].x, rb[i].y, h[i * 2],     l[i * 2]);                 \
            packhl(rb[i].z, rb[i].w, h[i * 2 + 1], l[i * 2 + 1]);             \
        }                                                                     \
        STS4((bb) + OFF_BH + o0, h[0], h[1], h[2], h[3]);                     \
        STS4((bb) + OFF_BH + o1, h[4], h[5], h[6], h[7]);                     \
        STS4((bb) + OFF_BL + o0, l[0], l[1], l[2], l[3]);                     \
        STS4((bb) + OFF_BL + o1, l[4], l[5], l[6], l[7]);                     \
    }

#define GEMM_MAINLOOP()                                                       \
    float4 ra[4], rb[4];                                                      \
    GEMM_LDG(0);                                                              \
    GEMM_STS(sbase);                                                          \
    __syncthreads();                                                          \
    _Pragma("unroll 1")                                                       \
    for (int s = 0; s < 24; s++) {                                            \
        const uint32_t cur = sbase + (uint32_t)(s & 1) * BUFSZ;               \
        const uint32_t nxt = sbase + (uint32_t)((s + 1) & 1) * BUFSZ;         \
        if (s + 1 < 24) GEMM_LDG(s + 1);                                      \
        COMP_KB(0, cur);                                                      \
        COMP_KB(1, cur);                                                      \
        if (s + 1 < 24) GEMM_STS(nxt);                                        \
        __syncthreads();                                                      \
    }

// ===========================================================================
// Kernel A: QKV GEMM (HMMA split-bf16) + fused RoPE + [B,H,T,DH] transpose.
// grid (18, 64): x = mat*6 + ntile, y = mtile. 256 threads. dyn smem 64KB.
// ===========================================================================
__global__ __launch_bounds__(256, 1) void qkv_tc(
    const float* __restrict__ x,
    const float* __restrict__ wq, const float* __restrict__ wk,
    const float* __restrict__ wv,
    const float* __restrict__ cosb, const float* __restrict__ sinb)
{
    GEMM_SETUP();
    const int mat = blockIdx.x / 6, ntm = blockIdx.x % 6;
    const int m0 = blockIdx.y * 128, n0 = ntm * 128;
    const float* W = (mat == 0) ? wq : ((mat == 1) ? wk : wv);
    const float* gA = x + (size_t)m0 * DMn;
    const float* gB = W + (size_t)n0 * DMn;

    GEMM_MAINLOOP();

    float* dstmat = (mat == 0) ? g_q : ((mat == 1) ? g_k : g_v);
    const bool rope = (mat < 2);
    #pragma unroll
    for (int mt = 0; mt < 2; mt++) {
        const int r0 = m0 + mw * 32 + mt * 16 + (lane >> 2);
        #pragma unroll
        for (int half = 0; half < 2; half++) {
            const int m = r0 + half * 8;
            const int b = m >> 11, tt = m & 2047;
            #pragma unroll
            for (int nt = 0; nt < 8; nt++) {
                const int colN = n0 + nw * 64 + nt * 8 + (lane & 3) * 2;
                const int head = colN >> 6, dh = colN & 63, pi = dh >> 1;
                float v0 = c[mt][nt][half * 2 + 0];
                float v1 = c[mt][nt][half * 2 + 1];
                float2 o;
                if (rope) {
                    float cs = cosb[tt * 32 + pi], sn = sinb[tt * 32 + pi];
                    o.x = v0 * cs - v1 * sn;
                    o.y = v0 * sn + v1 * cs;
                } else {
                    o.x = v0; o.y = v1;
                }
                *(float2*)(dstmat +
                    ((size_t)(b * Hn + head) * Tn + tt) * DHn + dh) = o;
            }
        }
    }
}

// ===========================================================================
// Kernel C: output projection (HMMA split-bf16). grid (6, 64).
// ===========================================================================
__global__ __launch_bounds__(256, 1) void proj_tc(
    const float* __restrict__ wo, float* __restrict__ out)
{
    GEMM_SETUP();
    const int m0 = blockIdx.y * 128, n0 = blockIdx.x * 128;
    const float* gA = g_o + (size_t)m0 * DMn;
    const float* gB = wo  + (size_t)n0 * DMn;

    GEMM_MAINLOOP();

    #pragma unroll
    for (int mt = 0; mt < 2; mt++) {
        const int r0 = m0 + mw * 32 + mt * 16 + (lane >> 2);
        #pragma unroll
        for (int half = 0; half < 2; half++) {
            const int m = r0 + half * 8;
            #pragma unroll
            for (int nt = 0; nt < 8; nt++) {
                const int colN = n0 + nw * 64 + nt * 8 + (lane & 3) * 2;
                *(float2*)(out + (size_t)m * DMn + colN) =
                    make_float2(c[mt][nt][half * 2], c[mt][nt][half * 2 + 1]);
            }
        }
    }
}

// ---------------------------------------------------------------------------
// Kernel B: causal flash attention, fp32 (unchanged round-2 baseline).
// ---------------------------------------------------------------------------
__global__ __launch_bounds__(128) void attn_kernel()
{
    __shared__ __align__(16) float Ks[32 * 64];
    __shared__ __align__(16) float Vs[32 * 64];

    const int qt  = (int)gridDim.x - 1 - (int)blockIdx.x;
    const int bh  = blockIdx.y;
    const int tid = threadIdx.x;
    const int t   = qt * 128 + tid;

    const float* qp = g_q + (bh * Tn + t) * DHn;
    float4 qv[16];
    #pragma unroll
    for (int i = 0; i < 16; i++) qv[i] = *(const float4*)(qp + i * 4);

    float4 av[16];
    #pragma unroll
    for (int i = 0; i < 16; i++) av[i] = make_float4(0.f, 0.f, 0.f, 0.f);

    float mx = -1e30f, l = 0.f;
    const float4* kb = (const float4*)(g_k + bh * Tn * DHn);
    const float4* vb = (const float4*)(g_v + bh * Tn * DHn);
    const int ktmax = 4 * qt + 3;
    float s[32];

    for (int kt = 0; kt <= ktmax; kt++) {
        #pragma unroll
        for (int i = 0; i < 4; i++) {
            ((float4*)Ks)[tid + i * 128] = kb[kt * 512 + tid + i * 128];
            ((float4*)Vs)[tid + i * 128] = vb[kt * 512 + tid + i * 128];
        }
        __syncthreads();

        float mtile = -1e30f;
        #pragma unroll 4
        for (int j = 0; j < 32; j++) {
            const float4* kr = (const float4*)(Ks + j * 64);
            float acc = 0.f;
            #pragma unroll
            for (int d = 0; d < 16; d++) {
                float4 k4 = kr[d];
                acc += qv[d].x * k4.x + qv[d].y * k4.y
                     + qv[d].z * k4.z + qv[d].w * k4.w;
            }
            acc *= 0.125f;
            if (kt * 32 + j > t) acc = -1e30f;
            s[j] = acc;
            mtile = fmaxf(mtile, acc);
        }

        float newm = fmaxf(mx, mtile);
        float corr = __expf(mx - newm);
        mx = newm;
        l *= corr;
        #pragma unroll
        for (int d = 0; d < 16; d++) {
            av[d].x *= corr; av[d].y *= corr; av[d].z *= corr; av[d].w *= corr;
        }

        #pragma unroll 4
        for (int j = 0; j < 32; j++) {
            float p = __expf(s[j] - mx);
            l += p;
            const float4* vr = (const float4*)(Vs + j * 64);
            #pragma unroll
            for (int d = 0; d < 16; d++) {
                float4 v4 = vr[d];
                av[d].x += p * v4.x; av[d].y += p * v4.y;
                av[d].z += p * v4.z; av[d].w += p * v4.w;
            }
        }
        __syncthreads();
    }

    float inv = 1.f / l;
    int b = bh / Hn, h = bh % Hn;
    float* op = g_o + (b * Tn + t) * DMn + h * DHn;
    #pragma unroll
    for (int d = 0; d < 16; d++) {
        *(float4*)(op + d * 4) =
            make_float4(av[d].x * inv, av[d].y * inv, av[d].z * inv, av[d].w * inv);
    }
}

// ---------------------------------------------------------------------------
extern "C" void kernel_launch(void* const* d_in, const int* in_sizes, int n_in,
                              void* d_out, int out_size)
{
    const float* x    = (const float*)d_in[0];
    const float* cosb = (const float*)d_in[1];
    const float* sinb = (const float*)d_in[2];
    const float* wq   = (const float*)d_in[3];
    const float* wk   = (const float*)d_in[4];
    const float* wv   = (const float*)d_in[5];
    const float* wo   = (const float*)d_in[6];
    float* out = (float*)d_out;

    cudaFuncSetAttribute(qkv_tc,
        cudaFuncAttributeMaxDynamicSharedMemorySize, 2 * BUFSZ);
    cudaFuncSetAttribute(proj_tc,
        cudaFuncAttributeMaxDynamicSharedMemorySize, 2 * BUFSZ);

    dim3 gA(18, 64);   // 3 mats x 6 ntiles, 64 mtiles
    qkv_tc<<<gA, 256, 2 * BUFSZ>>>(x, wq, wk, wv, cosb, sinb);

    dim3 gB(16, 48);   // 16 qtiles, B*H
    attn_kernel<<<gB, 128>>>();

    dim3 gC(6, 64);
    proj_tc<<<gC, 256, 2 * BUFSZ>>>(wo, out);
}

// round 6
// speedup vs baseline: 3.9866x; 2.0724x over previous
#include <cuda_runtime.h>
#include <cuda_bf16.h>
#include <cuda_fp16.h>
#include <cstdint>

#define Bn  4
#define Tn  2048
#define DMn 768
#define Hn  12
#define DHn 64

// Scratch (device globals — no allocation allowed in kernel_launch)
__device__ __align__(16) float g_q[Bn*Hn*Tn*DHn];
__device__ __align__(16) float g_k[Bn*Hn*Tn*DHn];
__device__ __align__(16) float g_v[Bn*Hn*Tn*DHn];
__device__ __align__(16) float g_o[Bn*Tn*DMn];

// ===========================================================================
// HMMA split-bf16 GEMM machinery (validated round 5).
// ===========================================================================
#define OFF_AH 0
#define OFF_AL 8192
#define OFF_BH 16384
#define OFF_BL 24576
#define BUFSZ  32768

__device__ __forceinline__ uint32_t smem_u32(const void* p) {
    uint32_t a;
    asm("{ .reg .u64 t; cvta.to.shared.u64 t, %1; cvt.u32.u64 %0, t; }"
        : "=r"(a) : "l"(p));
    return a;
}

#define SWZ(row, chunk) \
    ((uint32_t)((row) * 64 + ((((chunk) ^ (((row) >> 1) & 3)) & 3) * 16)))

// 128B rows, 8 chunks of 16B, xor-by-row swizzle (attention tiles)
#define SWZA(row, chunk) \
    ((uint32_t)((row) * 128 + ((((chunk) ^ ((row) & 7)) & 7) * 16)))

__device__ __forceinline__ void packhl(float x0, float x1,
                                       uint32_t& h, uint32_t& l) {
    __nv_bfloat16 h0 = __float2bfloat16(x0), h1 = __float2bfloat16(x1);
    float r0 = x0 - __bfloat162float(h0), r1 = x1 - __bfloat162float(h1);
    __nv_bfloat16 l0 = __float2bfloat16(r0), l1 = __float2bfloat16(r1);
    h = (uint32_t)__bfloat16_as_ushort(h0) |
        ((uint32_t)__bfloat16_as_ushort(h1) << 16);
    l = (uint32_t)__bfloat16_as_ushort(l0) |
        ((uint32_t)__bfloat16_as_ushort(l1) << 16);
}

// fp16 hi/lo pack: lo gets x - half(x)
__device__ __forceinline__ void packhl_f16(float x0, float x1,
                                           uint32_t& h, uint32_t& l) {
    float h0 = __half2float(__float2half_rn(x0));
    float h1 = __half2float(__float2half_rn(x1));
    float r0 = x0 - h0, r1 = x1 - h1;
    asm("cvt.rn.f16x2.f32 %0, %1, %2;" : "=r"(h) : "f"(h1), "f"(h0));
    asm("cvt.rn.f16x2.f32 %0, %1, %2;" : "=r"(l) : "f"(r1), "f"(r0));
}

#define CVT_F16X2(res, a, b) \
    asm("cvt.rn.f16x2.f32 %0, %1, %2;" : "=r"(res) : "f"(b), "f"(a))

#define STS4(addr, r0, r1, r2, r3) \
    asm volatile("st.shared.v4.b32 [%0], {%1, %2, %3, %4};" \
        :: "r"(addr), "r"(r0), "r"(r1), "r"(r2), "r"(r3) : "memory")

#define LDSM4(r, addr) \
    asm volatile("ldmatrix.sync.aligned.m8n8.x4.shared.b16 {%0,%1,%2,%3}, [%4];" \
        : "=r"((r)[0]), "=r"((r)[1]), "=r"((r)[2]), "=r"((r)[3]) : "r"(addr))

#define LDSMT4(r, addr) \
    asm volatile("ldmatrix.sync.aligned.m8n8.x4.trans.shared.b16 {%0,%1,%2,%3}, [%4];" \
        : "=r"((r)[0]), "=r"((r)[1]), "=r"((r)[2]), "=r"((r)[3]) : "r"(addr))

#define MMA1(cc, a, b0r, b1r) \
    asm volatile("mma.sync.aligned.m16n8k16.row.col.f32.bf16.bf16.f32 " \
        "{%0,%1,%2,%3}, {%4,%5,%6,%7}, {%8,%9}, {%0,%1,%2,%3};" \
        : "+f"((cc)[0]), "+f"((cc)[1]), "+f"((cc)[2]), "+f"((cc)[3]) \
        : "r"((a)[0]), "r"((a)[1]), "r"((a)[2]), "r"((a)[3]), \
          "r"(b0r), "r"(b1r))

#define MMA1H(cc, a, b0r, b1r) \
    asm volatile("mma.sync.aligned.m16n8k16.row.col.f32.f16.f16.f32 " \
        "{%0,%1,%2,%3}, {%4,%5,%6,%7}, {%8,%9}, {%0,%1,%2,%3};" \
        : "+f"((cc)[0]), "+f"((cc)[1]), "+f"((cc)[2]), "+f"((cc)[3]) \
        : "r"((a)[0]), "r"((a)[1]), "r"((a)[2]), "r"((a)[3]), \
          "r"(b0r), "r"(b1r))

#define MMA_ALL(AF, BF) \
    _Pragma("unroll") \
    for (int mt = 0; mt < 2; mt++) \
        _Pragma("unroll") \
        for (int nt = 0; nt < 8; nt++) \
            MMA1(c[mt][nt], (AF)[mt], (BF)[nt >> 1][(nt & 1) * 2], \
                 (BF)[nt >> 1][(nt & 1) * 2 + 1]);

#define COMP_KB(kb, SBASE) do {                                               \
    uint32_t aF[2][4], bF[4][4], aT[2][4], bT[4][4];                          \
    _Pragma("unroll")                                                         \
    for (int mt = 0; mt < 2; mt++)                                            \
        LDSM4(aF[mt], (SBASE) + OFF_AH +                                      \
              SWZ(mw * 32 + mt * 16 + a_r, (kb) * 2 + a_cb));                 \
    _Pragma("unroll")                                                         \
    for (int np = 0; np < 4; np++)                                            \
        LDSM4(bF[np], (SBASE) + OFF_BH +                                      \
              SWZ(nw * 64 + np * 16 + b_off, (kb) * 2 + b_cb));               \
    MMA_ALL(aF, bF);                                                          \
    _Pragma("unroll")                                                         \
    for (int mt = 0; mt < 2; mt++)                                            \
        LDSM4(aT[mt], (SBASE) + OFF_AL +                                      \
              SWZ(mw * 32 + mt * 16 + a_r, (kb) * 2 + a_cb));                 \
    MMA_ALL(aT, bF);                                                          \
    _Pragma("unroll")                                                         \
    for (int np = 0; np < 4; np++)                                            \
        LDSM4(bT[np], (SBASE) + OFF_BL +                                      \
              SWZ(nw * 64 + np * 16 + b_off, (kb) * 2 + b_cb));               \
    MMA_ALL(aF, bT);                                                          \
} while (0)

#define GEMM_SETUP()                                                          \
    extern __shared__ unsigned char dynsm[];                                  \
    const uint32_t sbase = smem_u32(dynsm);                                   \
    const int tid = threadIdx.x, lane = tid & 31, wid = tid >> 5;             \
    const int mw = wid & 3, nw = wid >> 2;                                    \
    const int a_r = lane & 15, a_cb = lane >> 4;                              \
    const int b_off = ((lane >> 4) << 3) + (lane & 7), b_cb = (lane >> 3) & 1;\
    const int ldrow = tid >> 1, ldhalf = tid & 1;                             \
    float c[2][8][4];                                                         \
    _Pragma("unroll")                                                         \
    for (int i = 0; i < 2; i++)                                               \
        _Pragma("unroll")                                                     \
        for (int j = 0; j < 8; j++)                                           \
            _Pragma("unroll")                                                 \
            for (int q = 0; q < 4; q++) c[i][j][q] = 0.f;

#define GEMM_LDG(s)                                                           \
    {                                                                         \
        const float4* pa = (const float4*)(gA + (size_t)ldrow * DMn +         \
                                           (s) * 32 + ldhalf * 16);           \
        const float4* pb = (const float4*)(gB + (size_t)ldrow * DMn +         \
                                           (s) * 32 + ldhalf * 16);           \
        ra[0] = pa[0]; ra[1] = pa[1]; ra[2] = pa[2]; ra[3] = pa[3];           \
        rb[0] = pb[0]; rb[1] = pb[1]; rb[2] = pb[2]; rb[3] = pb[3];           \
    }

#define GEMM_STS(bb)                                                          \
    {                                                                         \
        uint32_t h[8], l[8];                                                  \
        _Pragma("unroll")                                                     \
        for (int i = 0; i < 4; i++) {                                         \
            packhl(ra[i].x, ra[i].y, h[i * 2],     l[i * 2]);                 \
            packhl(ra[i].z, ra[i].w, h[i * 2 + 1], l[i * 2 + 1]);             \
        }                                                                     \
        uint32_t o0 = SWZ(ldrow, ldhalf * 2), o1 = SWZ(ldrow, ldhalf * 2 + 1);\
        STS4((bb) + OFF_AH + o0, h[0], h[1], h[2], h[3]);                     \
        STS4((bb) + OFF_AH + o1, h[4], h[5], h[6], h[7]);                     \
        STS4((bb) + OFF_AL + o0, l[0], l[1], l[2], l[3]);                     \
        STS4((bb) + OFF_AL + o1, l[4], l[5], l[6], l[7]);                     \
        _Pragma("unroll")                                                     \
        for (int i = 0; i < 4; i++) {                                         \
            packhl(rb[i].x, rb[i].y, h[i * 2],     l[i * 2]);                 \
            packhl(rb[i].z, rb[i].w, h[i * 2 + 1], l[i * 2 + 1]);             \
        }                                                                     \
        STS4((bb) + OFF_BH + o0, h[0], h[1], h[2], h[3]);                     \
        STS4((bb) + OFF_BH + o1, h[4], h[5], h[6], h[7]);                     \
        STS4((bb) + OFF_BL + o0, l[0], l[1], l[2], l[3]);                     \
        STS4((bb) + OFF_BL + o1, l[4], l[5], l[6], l[7]);                     \
    }

#define GEMM_MAINLOOP()                                                       \
    float4 ra[4], rb[4];                                                      \
    GEMM_LDG(0);                                                              \
    GEMM_STS(sbase);                                                          \
    __syncthreads();                                                          \
    _Pragma("unroll 1")                                                       \
    for (int s = 0; s < 24; s++) {                                            \
        const uint32_t cur = sbase + (uint32_t)(s & 1) * BUFSZ;               \
        const uint32_t nxt = sbase + (uint32_t)((s + 1) & 1) * BUFSZ;         \
        if (s + 1 < 24) GEMM_LDG(s + 1);                                      \
        COMP_KB(0, cur);                                                      \
        COMP_KB(1, cur);                                                      \
        if (s + 1 < 24) GEMM_STS(nxt);                                        \
        __syncthreads();                                                      \
    }

// ===========================================================================
// Kernel A: QKV GEMM (HMMA split-bf16) + fused RoPE + [B,H,T,DH] transpose.
// ===========================================================================
__global__ __launch_bounds__(256, 1) void qkv_tc(
    const float* __restrict__ x,
    const float* __restrict__ wq, const float* __restrict__ wk,
    const float* __restrict__ wv,
    const float* __restrict__ cosb, const float* __restrict__ sinb)
{
    GEMM_SETUP();
    const int mat = blockIdx.x / 6, ntm = blockIdx.x % 6;
    const int m0 = blockIdx.y * 128, n0 = ntm * 128;
    const float* W = (mat == 0) ? wq : ((mat == 1) ? wk : wv);
    const float* gA = x + (size_t)m0 * DMn;
    const float* gB = W + (size_t)n0 * DMn;

    GEMM_MAINLOOP();

    float* dstmat = (mat == 0) ? g_q : ((mat == 1) ? g_k : g_v);
    const bool rope = (mat < 2);
    #pragma unroll
    for (int mt = 0; mt < 2; mt++) {
        const int r0 = m0 + mw * 32 + mt * 16 + (lane >> 2);
        #pragma unroll
        for (int half = 0; half < 2; half++) {
            const int m = r0 + half * 8;
            const int b = m >> 11, tt = m & 2047;
            #pragma unroll
            for (int nt = 0; nt < 8; nt++) {
                const int colN = n0 + nw * 64 + nt * 8 + (lane & 3) * 2;
                const int head = colN >> 6, dh = colN & 63, pi = dh >> 1;
                float v0 = c[mt][nt][half * 2 + 0];
                float v1 = c[mt][nt][half * 2 + 1];
                float2 o;
                if (rope) {
                    float cs = cosb[tt * 32 + pi], sn = sinb[tt * 32 + pi];
                    o.x = v0 * cs - v1 * sn;
                    o.y = v0 * sn + v1 * cs;
                } else {
                    o.x = v0; o.y = v1;
                }
                *(float2*)(dstmat +
                    ((size_t)(b * Hn + head) * Tn + tt) * DHn + dh) = o;
            }
        }
    }
}

// ===========================================================================
// Kernel C: output projection (HMMA split-bf16). grid (6, 64).
// ===========================================================================
__global__ __launch_bounds__(256, 1) void proj_tc(
    const float* __restrict__ wo, float* __restrict__ out)
{
    GEMM_SETUP();
    const int m0 = blockIdx.y * 128, n0 = blockIdx.x * 128;
    const float* gA = g_o + (size_t)m0 * DMn;
    const float* gB = wo  + (size_t)n0 * DMn;

    GEMM_MAINLOOP();

    #pragma unroll
    for (int mt = 0; mt < 2; mt++) {
        const int r0 = m0 + mw * 32 + mt * 16 + (lane >> 2);
        #pragma unroll
        for (int half = 0; half < 2; half++) {
            const int m = r0 + half * 8;
            #pragma unroll
            for (int nt = 0; nt < 8; nt++) {
                const int colN = n0 + nw * 64 + nt * 8 + (lane & 3) * 2;
                *(float2*)(out + (size_t)m * DMn + colN) =
                    make_float2(c[mt][nt][half * 2], c[mt][nt][half * 2 + 1]);
            }
        }
    }
}

// ===========================================================================
// Kernel B: causal flash attention via HMMA.
// S = Q·K^T split-bf16 (3 terms); P·V fp16 with split-V (2 terms).
// CTA: 128 queries (8 warps x 16 rows), key tiles of 64. grid (16, 48).
// smem: Qh/Ql 16KB each, Kh/Kl 8KB each (bf16), Vh/Vl 8KB each (fp16) = 64KB.
// ===========================================================================
#define AQ_H 0
#define AQ_L 16384
#define AK_H 32768
#define AK_L 40960
#define AV_H 49152
#define AV_L 57344
#define ATT_SMEM 65536

__global__ __launch_bounds__(256, 1) void attn_tc()
{
    extern __shared__ unsigned char dynsm[];
    const uint32_t sb = smem_u32(dynsm);
    const int tid = threadIdx.x, lane = tid & 31, mw = tid >> 5;
    const int qt = 15 - (int)blockIdx.x;
    const int bh = blockIdx.y;
    const int q0 = qt * 128;
    const int b_off = ((lane >> 4) << 3) + (lane & 7);
    const int b_cb  = (lane >> 3) & 1;

    // ---- stage Q tile (128 x 64) as split-bf16 ----
    {
        const int row = tid >> 1, half = tid & 1;
        const float4* qp = (const float4*)(g_q +
            ((size_t)bh * Tn + q0 + row) * DHn + half * 32);
        float4 v[8];
        #pragma unroll
        for (int i = 0; i < 8; i++) v[i] = qp[i];
        uint32_t h[16], l[16];
        #pragma unroll
        for (int i = 0; i < 8; i++) {
            packhl(v[i].x, v[i].y, h[i*2],   l[i*2]);
            packhl(v[i].z, v[i].w, h[i*2+1], l[i*2+1]);
        }
        #pragma unroll
        for (int c4 = 0; c4 < 4; c4++) {
            uint32_t o = SWZA(row, half * 4 + c4);
            STS4(sb + AQ_H + o, h[c4*4], h[c4*4+1], h[c4*4+2], h[c4*4+3]);
            STS4(sb + AQ_L + o, l[c4*4], l[c4*4+1], l[c4*4+2], l[c4*4+3]);
        }
    }
    __syncthreads();

    // ---- per-warp Q A-fragments (rows mw*16..+15, all 64 dh) ----
    uint32_t aQh[4][4], aQl[4][4];
    #pragma unroll
    for (int kc = 0; kc < 4; kc++) {
        uint32_t o = SWZA(mw * 16 + (lane & 15), kc * 2 + (lane >> 4));
        LDSM4(aQh[kc], sb + AQ_H + o);
        LDSM4(aQl[kc], sb + AQ_L + o);
    }

    float co[8][4];
    #pragma unroll
    for (int i = 0; i < 8; i++)
        #pragma unroll
        for (int j = 0; j < 4; j++) co[i][j] = 0.f;
    float m0 = -1e30f, m1 = -1e30f, l0 = 0.f, l1 = 0.f;
    const int rowq = q0 + mw * 16 + (lane >> 2);
    const int nkt = 2 * qt + 2;

    for (int kt = 0; kt < nkt; kt++) {
        // ---- load K,V tile (64 keys x 64 dh) ----
        const int krow = tid >> 2, kq = tid & 3;
        const float4* kp = (const float4*)(g_k +
            ((size_t)bh * Tn + kt * 64 + krow) * DHn + kq * 16);
        const float4* vp = (const float4*)(g_v +
            ((size_t)bh * Tn + kt * 64 + krow) * DHn + kq * 16);
        float4 kv[4], vv[4];
        #pragma unroll
        for (int i = 0; i < 4; i++) { kv[i] = kp[i]; vv[i] = vp[i]; }
        __syncthreads();   // previous tile's smem reads complete
        {
            uint32_t h[8], l[8];
            #pragma unroll
            for (int i = 0; i < 4; i++) {
                packhl(kv[i].x, kv[i].y, h[i*2],   l[i*2]);
                packhl(kv[i].z, kv[i].w, h[i*2+1], l[i*2+1]);
            }
            uint32_t o0 = SWZA(krow, kq * 2), o1 = SWZA(krow, kq * 2 + 1);
            STS4(sb + AK_H + o0, h[0], h[1], h[2], h[3]);
            STS4(sb + AK_H + o1, h[4], h[5], h[6], h[7]);
            STS4(sb + AK_L + o0, l[0], l[1], l[2], l[3]);
            STS4(sb + AK_L + o1, l[4], l[5], l[6], l[7]);
            #pragma unroll
            for (int i = 0; i < 4; i++) {
                packhl_f16(vv[i].x, vv[i].y, h[i*2],   l[i*2]);
                packhl_f16(vv[i].z, vv[i].w, h[i*2+1], l[i*2+1]);
            }
            STS4(sb + AV_H + o0, h[0], h[1], h[2], h[3]);
            STS4(sb + AV_H + o1, h[4], h[5], h[6], h[7]);
            STS4(sb + AV_L + o0, l[0], l[1], l[2], l[3]);
            STS4(sb + AV_L + o1, l[4], l[5], l[6], l[7]);
        }
        __syncthreads();

        // ---- S = Q·K^T (split-bf16, 3 terms) ----
        float cs[8][4];
        #pragma unroll
        for (int i = 0; i < 8; i++)
            #pragma unroll
            for (int j = 0; j < 4; j++) cs[i][j] = 0.f;
        #pragma unroll
        for (int kc = 0; kc < 4; kc++) {
            uint32_t bKh[4][4], bKl[4][4];
            #pragma unroll
            for (int np = 0; np < 4; np++)
                LDSM4(bKh[np], sb + AK_H +
                      SWZA(np * 16 + b_off, kc * 2 + b_cb));
            #pragma unroll
            for (int nt = 0; nt < 8; nt++)
                MMA1(cs[nt], aQh[kc], bKh[nt>>1][(nt&1)*2],
                     bKh[nt>>1][(nt&1)*2+1]);
            #pragma unroll
            for (int nt = 0; nt < 8; nt++)
                MMA1(cs[nt], aQl[kc], bKh[nt>>1][(nt&1)*2],
                     bKh[nt>>1][(nt&1)*2+1]);
            #pragma unroll
            for (int np = 0; np < 4; np++)
                LDSM4(bKl[np], sb + AK_L +
                      SWZA(np * 16 + b_off, kc * 2 + b_cb));
            #pragma unroll
            for (int nt = 0; nt < 8; nt++)
                MMA1(cs[nt], aQh[kc], bKl[nt>>1][(nt&1)*2],
                     bKl[nt>>1][(nt&1)*2+1]);
        }

        // ---- softmax (online, fp32 fragments) ----
        const bool domask = (kt >= 2 * qt);
        float mt0 = -1e30f, mt1 = -1e30f;
        #pragma unroll
        for (int nt = 0; nt < 8; nt++) {
            const int ck = kt * 64 + nt * 8 + (lane & 3) * 2;
            float s0 = cs[nt][0] * 0.125f, s1 = cs[nt][1] * 0.125f;
            float s2 = cs[nt][2] * 0.125f, s3 = cs[nt][3] * 0.125f;
            if (domask) {
                if (ck     > rowq)     s0 = -1e30f;
                if (ck + 1 > rowq)     s1 = -1e30f;
                if (ck     > rowq + 8) s2 = -1e30f;
                if (ck + 1 > rowq + 8) s3 = -1e30f;
            }
            cs[nt][0] = s0; cs[nt][1] = s1; cs[nt][2] = s2; cs[nt][3] = s3;
            mt0 = fmaxf(mt0, fmaxf(s0, s1));
            mt1 = fmaxf(mt1, fmaxf(s2, s3));
        }
        mt0 = fmaxf(mt0, __shfl_xor_sync(0xffffffffu, mt0, 1));
        mt0 = fmaxf(mt0, __shfl_xor_sync(0xffffffffu, mt0, 2));
        mt1 = fmaxf(mt1, __shfl_xor_sync(0xffffffffu, mt1, 1));
        mt1 = fmaxf(mt1, __shfl_xor_sync(0xffffffffu, mt1, 2));
        const float nm0 = fmaxf(m0, mt0), nm1 = fmaxf(m1, mt1);
        const float cr0 = __expf(m0 - nm0), cr1 = __expf(m1 - nm1);
        m0 = nm0; m1 = nm1; l0 *= cr0; l1 *= cr1;

        uint32_t aP[4][4];
        #pragma unroll
        for (int nt = 0; nt < 8; nt++) {
            float p0 = __expf(cs[nt][0] - m0), p1 = __expf(cs[nt][1] - m0);
            float p2 = __expf(cs[nt][2] - m1), p3 = __expf(cs[nt][3] - m1);
            l0 += p0 + p1; l1 += p2 + p3;
            CVT_F16X2(aP[nt >> 1][(nt & 1) * 2],     p0, p1);
            CVT_F16X2(aP[nt >> 1][(nt & 1) * 2 + 1], p2, p3);
        }
        #pragma unroll
        for (int nt = 0; nt < 8; nt++) {
            co[nt][0] *= cr0; co[nt][1] *= cr0;
            co[nt][2] *= cr1; co[nt][3] *= cr1;
        }

        // ---- O += P·V (fp16, V split 2 terms) ----
        #pragma unroll
        for (int kc = 0; kc < 4; kc++) {
            uint32_t bVh[4][4], bVl[4][4];
            const uint32_t vrow = kc * 16 + ((lane >> 3) & 1) * 8 + (lane & 7);
            #pragma unroll
            for (int g = 0; g < 4; g++)
                LDSMT4(bVh[g], sb + AV_H + SWZA(vrow, 2 * g + (lane >> 4)));
            #pragma unroll
            for (int nt = 0; nt < 8; nt++)
                MMA1H(co[nt], aP[kc], bVh[nt>>1][(nt&1)*2],
                      bVh[nt>>1][(nt&1)*2+1]);
            #pragma unroll
            for (int g = 0; g < 4; g++)
                LDSMT4(bVl[g], sb + AV_L + SWZA(vrow, 2 * g + (lane >> 4)));
            #pragma unroll
            for (int nt = 0; nt < 8; nt++)
                MMA1H(co[nt], aP[kc], bVl[nt>>1][(nt&1)*2],
                      bVl[nt>>1][(nt&1)*2+1]);
        }
    }

    // ---- finalize: row sums + write g_o ----
    l0 += __shfl_xor_sync(0xffffffffu, l0, 1);
    l0 += __shfl_xor_sync(0xffffffffu, l0, 2);
    l1 += __shfl_xor_sync(0xffffffffu, l1, 1);
    l1 += __shfl_xor_sync(0xffffffffu, l1, 2);
    const float i0 = 1.f / l0, i1 = 1.f / l1;
    const int b = bh / Hn, h = bh % Hn;
    const int t0 = q0 + mw * 16 + (lane >> 2);
    float* op0 = g_o + ((size_t)(b * Tn + t0)     * DMn) + h * DHn;
    float* op1 = g_o + ((size_t)(b * Tn + t0 + 8) * DMn) + h * DHn;
    #pragma unroll
    for (int nt = 0; nt < 8; nt++) {
        const int dh = nt * 8 + (lane & 3) * 2;
        *(float2*)(op0 + dh) = make_float2(co[nt][0] * i0, co[nt][1] * i0);
        *(float2*)(op1 + dh) = make_float2(co[nt][2] * i1, co[nt][3] * i1);
    }
}

// ---------------------------------------------------------------------------
extern "C" void kernel_launch(void* const* d_in, const int* in_sizes, int n_in,
                              void* d_out, int out_size)
{
    const float* x    = (const float*)d_in[0];
    const float* cosb = (const float*)d_in[1];
    const float* sinb = (const float*)d_in[2];
    const float* wq   = (const float*)d_in[3];
    const float* wk   = (const float*)d_in[4];
    const float* wv   = (const float*)d_in[5];
    const float* wo   = (const float*)d_in[6];
    float* out = (float*)d_out;

    cudaFuncSetAttribute(qkv_tc,
        cudaFuncAttributeMaxDynamicSharedMemorySize, 2 * BUFSZ);
    cudaFuncSetAttribute(proj_tc,
        cudaFuncAttributeMaxDynamicSharedMemorySize, 2 * BUFSZ);
    cudaFuncSetAttribute(attn_tc,
        cudaFuncAttributeMaxDynamicSharedMemorySize, ATT_SMEM);

    dim3 gA(18, 64);
    qkv_tc<<<gA, 256, 2 * BUFSZ>>>(x, wq, wk, wv, cosb, sinb);

    dim3 gB(16, 48);
    attn_tc<<<gB, 256, ATT_SMEM>>>();

    dim3 gC(6, 64);
    proj_tc<<<gC, 256, 2 * BUFSZ>>>(wo, out);
}

// round 7
// speedup vs baseline: 4.7024x; 1.1796x over previous
#include <cuda_runtime.h>
#include <cuda_bf16.h>
#include <cuda_fp16.h>
#include <cstdint>

#define Bn  4
#define Tn  2048
#define DMn 768
#define Hn  12
#define DHn 64
#define QKVSZ (Bn*Hn*Tn*DHn)
#define XSZ   (Bn*Tn*DMn)
#define WSZ   (DMn*DMn)

// Scratch (device globals — no allocation allowed in kernel_launch)
__device__ __align__(16) __nv_bfloat16 g_xh[XSZ],  g_xl[XSZ];
__device__ __align__(16) __nv_bfloat16 g_wqh[WSZ], g_wql[WSZ];
__device__ __align__(16) __nv_bfloat16 g_wkh[WSZ], g_wkl[WSZ];
__device__ __align__(16) __nv_bfloat16 g_wvh[WSZ], g_wvl[WSZ];
__device__ __align__(16) __nv_bfloat16 g_woh[WSZ], g_wol[WSZ];
__device__ __align__(16) __nv_bfloat16 g_qh[QKVSZ], g_ql[QKVSZ];
__device__ __align__(16) __nv_bfloat16 g_kh[QKVSZ], g_kl[QKVSZ];
__device__ __align__(16) __half        g_vh[QKVSZ], g_vl[QKVSZ];
__device__ __align__(16) __nv_bfloat16 g_oh[XSZ],  g_ol[XSZ];

// ===========================================================================
// helpers
// ===========================================================================
__device__ __forceinline__ uint32_t smem_u32(const void* p) {
    uint32_t a;
    asm("{ .reg .u64 t; cvta.to.shared.u64 t, %1; cvt.u32.u64 %0, t; }"
        : "=r"(a) : "l"(p));
    return a;
}

#define SWZ(row, chunk) \
    ((uint32_t)((row) * 64 + ((((chunk) ^ (((row) >> 1) & 3)) & 3) * 16)))

#define SWZA(row, chunk) \
    ((uint32_t)((row) * 128 + ((((chunk) ^ ((row) & 7)) & 7) * 16)))

__device__ __forceinline__ void packhl(float x0, float x1,
                                       uint32_t& h, uint32_t& l) {
    __nv_bfloat16 h0 = __float2bfloat16(x0), h1 = __float2bfloat16(x1);
    float r0 = x0 - __bfloat162float(h0), r1 = x1 - __bfloat162float(h1);
    __nv_bfloat16 l0 = __float2bfloat16(r0), l1 = __float2bfloat16(r1);
    h = (uint32_t)__bfloat16_as_ushort(h0) |
        ((uint32_t)__bfloat16_as_ushort(h1) << 16);
    l = (uint32_t)__bfloat16_as_ushort(l0) |
        ((uint32_t)__bfloat16_as_ushort(l1) << 16);
}

__device__ __forceinline__ void packhl_f16(float x0, float x1,
                                           uint32_t& h, uint32_t& l) {
    float h0 = __half2float(__float2half_rn(x0));
    float h1 = __half2float(__float2half_rn(x1));
    float r0 = x0 - h0, r1 = x1 - h1;
    asm("cvt.rn.f16x2.f32 %0, %1, %2;" : "=r"(h) : "f"(h1), "f"(h0));
    asm("cvt.rn.f16x2.f32 %0, %1, %2;" : "=r"(l) : "f"(r1), "f"(r0));
}

#define CVT_F16X2(res, a, b) \
    asm("cvt.rn.f16x2.f32 %0, %1, %2;" : "=r"(res) : "f"(b), "f"(a))

#define STS4(addr, r0, r1, r2, r3) \
    asm volatile("st.shared.v4.b32 [%0], {%1, %2, %3, %4};" \
        :: "r"(addr), "r"(r0), "r"(r1), "r"(r2), "r"(r3) : "memory")

#define LDSM4(r, addr) \
    asm volatile("ldmatrix.sync.aligned.m8n8.x4.shared.b16 {%0,%1,%2,%3}, [%4];" \
        : "=r"((r)[0]), "=r"((r)[1]), "=r"((r)[2]), "=r"((r)[3]) : "r"(addr))

#define LDSMT4(r, addr) \
    asm volatile("ldmatrix.sync.aligned.m8n8.x4.trans.shared.b16 {%0,%1,%2,%3}, [%4];" \
        : "=r"((r)[0]), "=r"((r)[1]), "=r"((r)[2]), "=r"((r)[3]) : "r"(addr))

#define MMA1(cc, a, b0r, b1r) \
    asm volatile("mma.sync.aligned.m16n8k16.row.col.f32.bf16.bf16.f32 " \
        "{%0,%1,%2,%3}, {%4,%5,%6,%7}, {%8,%9}, {%0,%1,%2,%3};" \
        : "+f"((cc)[0]), "+f"((cc)[1]), "+f"((cc)[2]), "+f"((cc)[3]) \
        : "r"((a)[0]), "r"((a)[1]), "r"((a)[2]), "r"((a)[3]), \
          "r"(b0r), "r"(b1r))

#define MMA1H(cc, a, b0r, b1r) \
    asm volatile("mma.sync.aligned.m16n8k16.row.col.f32.f16.f16.f32 " \
        "{%0,%1,%2,%3}, {%4,%5,%6,%7}, {%8,%9}, {%0,%1,%2,%3};" \
        : "+f"((cc)[0]), "+f"((cc)[1]), "+f"((cc)[2]), "+f"((cc)[3]) \
        : "r"((a)[0]), "r"((a)[1]), "r"((a)[2]), "r"((a)[3]), \
          "r"(b0r), "r"(b1r))

// ===========================================================================
// Split kernel: fp32 -> (hi, lo) bf16, elementwise over float4s.
// ===========================================================================
__global__ __launch_bounds__(256) void split_k(
    const float* __restrict__ src, __nv_bfloat16* __restrict__ h,
    __nv_bfloat16* __restrict__ l, int n4)
{
    const int i = blockIdx.x * 256 + threadIdx.x;
    if (i < n4) {
        float4 v = ((const float4*)src)[i];
        uint32_t h0, l0, h1, l1;
        packhl(v.x, v.y, h0, l0);
        packhl(v.z, v.w, h1, l1);
        ((uint2*)h)[i] = make_uint2(h0, h1);
        ((uint2*)l)[i] = make_uint2(l0, l1);
    }
}

// ===========================================================================
// GEMM core (pre-split bf16 inputs). 128x128 C, BK=32, 8 warps, 3 MMA terms.
// smem/buffer: Ah,Al,Bh,Bl 128x32 bf16 (8KB each) = 32KB; double buffered.
// ===========================================================================
#define OFF_AH 0
#define OFF_AL 8192
#define OFF_BH 16384
#define OFF_BL 24576
#define BUFSZ  32768

#define MMA_ALL(AF, BF) \
    _Pragma("unroll") \
    for (int mt = 0; mt < 2; mt++) \
        _Pragma("unroll") \
        for (int nt = 0; nt < 8; nt++) \
            MMA1(c[mt][nt], (AF)[mt], (BF)[nt >> 1][(nt & 1) * 2], \
                 (BF)[nt >> 1][(nt & 1) * 2 + 1]);

#define COMP_KB(kb, SBASE) do {                                               \
    uint32_t aF[2][4], bF[4][4], aT[2][4], bT[4][4];                          \
    _Pragma("unroll")                                                         \
    for (int mt = 0; mt < 2; mt++)                                            \
        LDSM4(aF[mt], (SBASE) + OFF_AH +                                      \
              SWZ(mw * 32 + mt * 16 + a_r, (kb) * 2 + a_cb));                 \
    _Pragma("unroll")                                                         \
    for (int np = 0; np < 4; np++)                                            \
        LDSM4(bF[np], (SBASE) + OFF_BH +                                      \
              SWZ(nw * 64 + np * 16 + b_off, (kb) * 2 + b_cb));               \
    MMA_ALL(aF, bF);                                                          \
    _Pragma("unroll")                                                         \
    for (int mt = 0; mt < 2; mt++)                                            \
        LDSM4(aT[mt], (SBASE) + OFF_AL +                                      \
              SWZ(mw * 32 + mt * 16 + a_r, (kb) * 2 + a_cb));                 \
    MMA_ALL(aT, bF);                                                          \
    _Pragma("unroll")                                                         \
    for (int np = 0; np < 4; np++)                                            \
        LDSM4(bT[np], (SBASE) + OFF_BL +                                      \
              SWZ(nw * 64 + np * 16 + b_off, (kb) * 2 + b_cb));               \
    MMA_ALL(aF, bT);                                                          \
} while (0)

#define GEMM_SETUP()                                                          \
    extern __shared__ unsigned char dynsm[];                                  \
    const uint32_t sbase = smem_u32(dynsm);                                   \
    const int tid = threadIdx.x, lane = tid & 31, wid = tid >> 5;             \
    const int mw = wid & 3, nw = wid >> 2;                                    \
    const int a_r = lane & 15, a_cb = lane >> 4;                              \
    const int b_off = ((lane >> 4) << 3) + (lane & 7), b_cb = (lane >> 3) & 1;\
    const int ldrow = tid >> 1, ldhalf = tid & 1;                             \
    float c[2][8][4];                                                         \
    _Pragma("unroll")                                                         \
    for (int i = 0; i < 2; i++)                                               \
        _Pragma("unroll")                                                     \
        for (int j = 0; j < 8; j++)                                           \
            _Pragma("unroll")                                                 \
            for (int q = 0; q < 4; q++) c[i][j][q] = 0.f;

// each thread: 32B (2x16B chunks) from each of Ah/Al/Bh/Bl rows
#define GEMM_LDG(s)                                                           \
    {                                                                         \
        const size_t ro = (size_t)ldrow * DMn + (s) * 32 + ldhalf * 16;       \
        const uint4* p;                                                       \
        p = (const uint4*)(gAh + ro); rah[0] = p[0]; rah[1] = p[1];           \
        p = (const uint4*)(gAl + ro); ral[0] = p[0]; ral[1] = p[1];           \
        p = (const uint4*)(gBh + ro); rbh[0] = p[0]; rbh[1] = p[1];           \
        p = (const uint4*)(gBl + ro); rbl[0] = p[0]; rbl[1] = p[1];           \
    }

#define GEMM_STS(bb)                                                          \
    {                                                                         \
        const uint32_t o0 = SWZ(ldrow, ldhalf * 2);                           \
        const uint32_t o1 = SWZ(ldrow, ldhalf * 2 + 1);                       \
        STS4((bb) + OFF_AH + o0, rah[0].x, rah[0].y, rah[0].z, rah[0].w);     \
        STS4((bb) + OFF_AH + o1, rah[1].x, rah[1].y, rah[1].z, rah[1].w);     \
        STS4((bb) + OFF_AL + o0, ral[0].x, ral[0].y, ral[0].z, ral[0].w);     \
        STS4((bb) + OFF_AL + o1, ral[1].x, ral[1].y, ral[1].z, ral[1].w);     \
        STS4((bb) + OFF_BH + o0, rbh[0].x, rbh[0].y, rbh[0].z, rbh[0].w);     \
        STS4((bb) + OFF_BH + o1, rbh[1].x, rbh[1].y, rbh[1].z, rbh[1].w);     \
        STS4((bb) + OFF_BL + o0, rbl[0].x, rbl[0].y, rbl[0].z, rbl[0].w);     \
        STS4((bb) + OFF_BL + o1, rbl[1].x, rbl[1].y, rbl[1].z, rbl[1].w);     \
    }

#define GEMM_MAINLOOP()                                                       \
    uint4 rah[2], ral[2], rbh[2], rbl[2];                                     \
    GEMM_LDG(0);                                                              \
    GEMM_STS(sbase);                                                          \
    __syncthreads();                                                          \
    _Pragma("unroll 1")                                                       \
    for (int s = 0; s < 24; s++) {                                            \
        const uint32_t cur = sbase + (uint32_t)(s & 1) * BUFSZ;               \
        const uint32_t nxt = sbase + (uint32_t)((s + 1) & 1) * BUFSZ;         \
        if (s + 1 < 24) GEMM_LDG(s + 1);                                      \
        COMP_KB(0, cur);                                                      \
        COMP_KB(1, cur);                                                      \
        if (s + 1 < 24) GEMM_STS(nxt);                                        \
        __syncthreads();                                                      \
    }

// ===========================================================================
// Kernel A: QKV GEMM + RoPE; writes split Q/K (bf16) and split V (fp16).
// grid (18, 64): x = mat*6 + ntile, y = mtile.
// ===========================================================================
__global__ __launch_bounds__(256, 1) void qkv_tc(
    const float* __restrict__ cosb, const float* __restrict__ sinb)
{
    GEMM_SETUP();
    const int mat = blockIdx.x / 6, ntm = blockIdx.x % 6;
    const int m0 = blockIdx.y * 128, n0 = ntm * 128;
    const __nv_bfloat16* gAh = g_xh + (size_t)m0 * DMn;
    const __nv_bfloat16* gAl = g_xl + (size_t)m0 * DMn;
    const __nv_bfloat16* gBh = ((mat == 0) ? g_wqh : (mat == 1) ? g_wkh : g_wvh)
                               + (size_t)n0 * DMn;
    const __nv_bfloat16* gBl = ((mat == 0) ? g_wql : (mat == 1) ? g_wkl : g_wvl)
                               + (size_t)n0 * DMn;

    GEMM_MAINLOOP();

    #pragma unroll
    for (int mt = 0; mt < 2; mt++) {
        const int r0 = m0 + mw * 32 + mt * 16 + (lane >> 2);
        #pragma unroll
        for (int half = 0; half < 2; half++) {
            const int m = r0 + half * 8;
            const int b = m >> 11, tt = m & 2047;
            #pragma unroll
            for (int nt = 0; nt < 8; nt++) {
                const int colN = n0 + nw * 64 + nt * 8 + (lane & 3) * 2;
                const int head = colN >> 6, dh = colN & 63, pi = dh >> 1;
                float v0 = c[mt][nt][half * 2 + 0];
                float v1 = c[mt][nt][half * 2 + 1];
                const size_t idx =
                    ((size_t)(b * Hn + head) * Tn + tt) * DHn + dh;
                uint32_t hh, ll;
                if (mat < 2) {
                    float cs = cosb[tt * 32 + pi], sn = sinb[tt * 32 + pi];
                    float o0 = v0 * cs - v1 * sn;
                    float o1 = v0 * sn + v1 * cs;
                    packhl(o0, o1, hh, ll);
                    if (mat == 0) {
                        *(uint32_t*)(g_qh + idx) = hh;
                        *(uint32_t*)(g_ql + idx) = ll;
                    } else {
                        *(uint32_t*)(g_kh + idx) = hh;
                        *(uint32_t*)(g_kl + idx) = ll;
                    }
                } else {
                    packhl_f16(v0, v1, hh, ll);
                    *(uint32_t*)(g_vh + idx) = hh;
                    *(uint32_t*)(g_vl + idx) = ll;
                }
            }
        }
    }
}

// ===========================================================================
// Kernel C: output projection; A = split O, B = split wo; fp32 out.
// ===========================================================================
__global__ __launch_bounds__(256, 1) void proj_tc(float* __restrict__ out)
{
    GEMM_SETUP();
    const int m0 = blockIdx.y * 128, n0 = blockIdx.x * 128;
    const __nv_bfloat16* gAh = g_oh + (size_t)m0 * DMn;
    const __nv_bfloat16* gAl = g_ol + (size_t)m0 * DMn;
    const __nv_bfloat16* gBh = g_woh + (size_t)n0 * DMn;
    const __nv_bfloat16* gBl = g_wol + (size_t)n0 * DMn;

    GEMM_MAINLOOP();

    #pragma unroll
    for (int mt = 0; mt < 2; mt++) {
        const int r0 = m0 + mw * 32 + mt * 16 + (lane >> 2);
        #pragma unroll
        for (int half = 0; half < 2; half++) {
            const int m = r0 + half * 8;
            #pragma unroll
            for (int nt = 0; nt < 8; nt++) {
                const int colN = n0 + nw * 64 + nt * 8 + (lane & 3) * 2;
                *(float2*)(out + (size_t)m * DMn + colN) =
                    make_float2(c[mt][nt][half * 2], c[mt][nt][half * 2 + 1]);
            }
        }
    }
}

// ===========================================================================
// Kernel B: causal flash attention via HMMA (pre-split inputs).
// ===========================================================================
#define AQ_H 0
#define AQ_L 16384
#define AK_H 32768
#define AK_L 40960
#define AV_H 49152
#define AV_L 57344
#define ATT_SMEM 65536

__global__ __launch_bounds__(256, 1) void attn_tc()
{
    extern __shared__ unsigned char dynsm[];
    const uint32_t sb = smem_u32(dynsm);
    const int tid = threadIdx.x, lane = tid & 31, mw = tid >> 5;
    const int qt = 15 - (int)blockIdx.x;
    const int bh = blockIdx.y;
    const int q0 = qt * 128;
    const int b_off = ((lane >> 4) << 3) + (lane & 7);
    const int b_cb  = (lane >> 3) & 1;

    // ---- stage Q tile (128 x 64 bf16 hi/lo): plain swizzled copy ----
    {
        const int row = tid >> 1, half = tid & 1;
        const size_t go = ((size_t)bh * Tn + q0 + row) * DHn + half * 32;
        const uint4* ph = (const uint4*)(g_qh + go);
        const uint4* pl = (const uint4*)(g_ql + go);
        #pragma unroll
        for (int c4 = 0; c4 < 4; c4++) {
            const uint32_t o = SWZA(row, half * 4 + c4);
            uint4 vh = ph[c4], vl = pl[c4];
            STS4(sb + AQ_H + o, vh.x, vh.y, vh.z, vh.w);
            STS4(sb + AQ_L + o, vl.x, vl.y, vl.z, vl.w);
        }
    }
    __syncthreads();

    uint32_t aQh[4][4], aQl[4][4];
    #pragma unroll
    for (int kc = 0; kc < 4; kc++) {
        const uint32_t o = SWZA(mw * 16 + (lane & 15), kc * 2 + (lane >> 4));
        LDSM4(aQh[kc], sb + AQ_H + o);
        LDSM4(aQl[kc], sb + AQ_L + o);
    }

    float co[8][4];
    #pragma unroll
    for (int i = 0; i < 8; i++)
        #pragma unroll
        for (int j = 0; j < 4; j++) co[i][j] = 0.f;
    float m0 = -1e30f, m1 = -1e30f, l0 = 0.f, l1 = 0.f;
    const int rowq = q0 + mw * 16 + (lane >> 2);
    const int nkt = 2 * qt + 2;

    for (int kt = 0; kt < nkt; kt++) {
        // ---- load K,V split tiles (64 x 64): plain swizzled copies ----
        const int krow = tid >> 2, kq = tid & 3;
        const size_t go = ((size_t)bh * Tn + kt * 64 + krow) * DHn + kq * 16;
        uint4 vkh[2], vkl[2], vvh[2], vvl[2];
        { const uint4* p = (const uint4*)(g_kh + go); vkh[0]=p[0]; vkh[1]=p[1]; }
        { const uint4* p = (const uint4*)(g_kl + go); vkl[0]=p[0]; vkl[1]=p[1]; }
        { const uint4* p = (const uint4*)(g_vh + go); vvh[0]=p[0]; vvh[1]=p[1]; }
        { const uint4* p = (const uint4*)(g_vl + go); vvl[0]=p[0]; vvl[1]=p[1]; }
        __syncthreads();   // previous tile's smem reads complete
        {
            const uint32_t o0 = SWZA(krow, kq * 2), o1 = SWZA(krow, kq * 2 + 1);
            STS4(sb + AK_H + o0, vkh[0].x, vkh[0].y, vkh[0].z, vkh[0].w);
            STS4(sb + AK_H + o1, vkh[1].x, vkh[1].y, vkh[1].z, vkh[1].w);
            STS4(sb + AK_L + o0, vkl[0].x, vkl[0].y, vkl[0].z, vkl[0].w);
            STS4(sb + AK_L + o1, vkl[1].x, vkl[1].y, vkl[1].z, vkl[1].w);
            STS4(sb + AV_H + o0, vvh[0].x, vvh[0].y, vvh[0].z, vvh[0].w);
            STS4(sb + AV_H + o1, vvh[1].x, vvh[1].y, vvh[1].z, vvh[1].w);
            STS4(sb + AV_L + o0, vvl[0].x, vvl[0].y, vvl[0].z, vvl[0].w);
            STS4(sb + AV_L + o1, vvl[1].x, vvl[1].y, vvl[1].z, vvl[1].w);
        }
        __syncthreads();

        // ---- S = Q·K^T (split-bf16, 3 terms) ----
        float cs[8][4];
        #pragma unroll
        for (int i = 0; i < 8; i++)
            #pragma unroll
            for (int j = 0; j < 4; j++) cs[i][j] = 0.f;
        #pragma unroll
        for (int kc = 0; kc < 4; kc++) {
            uint32_t bKh[4][4], bKl[4][4];
            #pragma unroll
            for (int np = 0; np < 4; np++)
                LDSM4(bKh[np], sb + AK_H +
                      SWZA(np * 16 + b_off, kc * 2 + b_cb));
            #pragma unroll
            for (int nt = 0; nt < 8; nt++)
                MMA1(cs[nt], aQh[kc], bKh[nt>>1][(nt&1)*2],
                     bKh[nt>>1][(nt&1)*2+1]);
            #pragma unroll
            for (int nt = 0; nt < 8; nt++)
                MMA1(cs[nt], aQl[kc], bKh[nt>>1][(nt&1)*2],
                     bKh[nt>>1][(nt&1)*2+1]);
            #pragma unroll
            for (int np = 0; np < 4; np++)
                LDSM4(bKl[np], sb + AK_L +
                      SWZA(np * 16 + b_off, kc * 2 + b_cb));
            #pragma unroll
            for (int nt = 0; nt < 8; nt++)
                MMA1(cs[nt], aQh[kc], bKl[nt>>1][(nt&1)*2],
                     bKl[nt>>1][(nt&1)*2+1]);
        }

        // ---- online softmax ----
        const bool domask = (kt >= 2 * qt);
        float mt0 = -1e30f, mt1 = -1e30f;
        #pragma unroll
        for (int nt = 0; nt < 8; nt++) {
            const int ck = kt * 64 + nt * 8 + (lane & 3) * 2;
            float s0 = cs[nt][0] * 0.125f, s1 = cs[nt][1] * 0.125f;
            float s2 = cs[nt][2] * 0.125f, s3 = cs[nt][3] * 0.125f;
            if (domask) {
                if (ck     > rowq)     s0 = -1e30f;
                if (ck + 1 > rowq)     s1 = -1e30f;
                if (ck     > rowq + 8) s2 = -1e30f;
                if (ck + 1 > rowq + 8) s3 = -1e30f;
            }
            cs[nt][0] = s0; cs[nt][1] = s1; cs[nt][2] = s2; cs[nt][3] = s3;
            mt0 = fmaxf(mt0, fmaxf(s0, s1));
            mt1 = fmaxf(mt1, fmaxf(s2, s3));
        }
        mt0 = fmaxf(mt0, __shfl_xor_sync(0xffffffffu, mt0, 1));
        mt0 = fmaxf(mt0, __shfl_xor_sync(0xffffffffu, mt0, 2));
        mt1 = fmaxf(mt1, __shfl_xor_sync(0xffffffffu, mt1, 1));
        mt1 = fmaxf(mt1, __shfl_xor_sync(0xffffffffu, mt1, 2));
        const float nm0 = fmaxf(m0, mt0), nm1 = fmaxf(m1, mt1);
        const float cr0 = __expf(m0 - nm0), cr1 = __expf(m1 - nm1);
        m0 = nm0; m1 = nm1; l0 *= cr0; l1 *= cr1;

        uint32_t aP[4][4];
        #pragma unroll
        for (int nt = 0; nt < 8; nt++) {
            float p0 = __expf(cs[nt][0] - m0), p1 = __expf(cs[nt][1] - m0);
            float p2 = __expf(cs[nt][2] - m1), p3 = __expf(cs[nt][3] - m1);
            l0 += p0 + p1; l1 += p2 + p3;
            CVT_F16X2(aP[nt >> 1][(nt & 1) * 2],     p0, p1);
            CVT_F16X2(aP[nt >> 1][(nt & 1) * 2 + 1], p2, p3);
        }
        #pragma unroll
        for (int nt = 0; nt < 8; nt++) {
            co[nt][0] *= cr0; co[nt][1] *= cr0;
            co[nt][2] *= cr1; co[nt][3] *= cr1;
        }

        // ---- O += P·V (fp16, split V, 2 terms) ----
        #pragma unroll
        for (int kc = 0; kc < 4; kc++) {
            uint32_t bVh[4][4], bVl[4][4];
            const uint32_t vrow = kc * 16 + ((lane >> 3) & 1) * 8 + (lane & 7);
            #pragma unroll
            for (int g = 0; g < 4; g++)
                LDSMT4(bVh[g], sb + AV_H + SWZA(vrow, 2 * g + (lane >> 4)));
            #pragma unroll
            for (int nt = 0; nt < 8; nt++)
                MMA1H(co[nt], aP[kc], bVh[nt>>1][(nt&1)*2],
                      bVh[nt>>1][(nt&1)*2+1]);
            #pragma unroll
            for (int g = 0; g < 4; g++)
                LDSMT4(bVl[g], sb + AV_L + SWZA(vrow, 2 * g + (lane >> 4)));
            #pragma unroll
            for (int nt = 0; nt < 8; nt++)
                MMA1H(co[nt], aP[kc], bVl[nt>>1][(nt&1)*2],
                      bVl[nt>>1][(nt&1)*2+1]);
        }
    }

    // ---- finalize: write split O ----
    l0 += __shfl_xor_sync(0xffffffffu, l0, 1);
    l0 += __shfl_xor_sync(0xffffffffu, l0, 2);
    l1 += __shfl_xor_sync(0xffffffffu, l1, 1);
    l1 += __shfl_xor_sync(0xffffffffu, l1, 2);
    const float i0 = 1.f / l0, i1 = 1.f / l1;
    const int b = bh / Hn, h = bh % Hn;
    const int t0 = q0 + mw * 16 + (lane >> 2);
    const size_t base0 = (size_t)(b * Tn + t0)     * DMn + h * DHn;
    const size_t base1 = (size_t)(b * Tn + t0 + 8) * DMn + h * DHn;
    #pragma unroll
    for (int nt = 0; nt < 8; nt++) {
        const int dh = nt * 8 + (lane & 3) * 2;
        uint32_t hh, ll;
        packhl(co[nt][0] * i0, co[nt][1] * i0, hh, ll);
        *(uint32_t*)(g_oh + base0 + dh) = hh;
        *(uint32_t*)(g_ol + base0 + dh) = ll;
        packhl(co[nt][2] * i1, co[nt][3] * i1, hh, ll);
        *(uint32_t*)(g_oh + base1 + dh) = hh;
        *(uint32_t*)(g_ol + base1 + dh) = ll;
    }
}

// ---------------------------------------------------------------------------
extern "C" void kernel_launch(void* const* d_in, const int* in_sizes, int n_in,
                              void* d_out, int out_size)
{
    const float* x    = (const float*)d_in[0];
    const float* cosb = (const float*)d_in[1];
    const float* sinb = (const float*)d_in[2];
    const float* wq   = (const float*)d_in[3];
    const float* wk   = (const float*)d_in[4];
    const float* wv   = (const float*)d_in[5];
    const float* wo   = (const float*)d_in[6];
    float* out = (float*)d_out;

    __nv_bfloat16 *p_xh, *p_xl, *p_wqh, *p_wql, *p_wkh, *p_wkl;
    __nv_bfloat16 *p_wvh, *p_wvl, *p_woh, *p_wol;
    cudaGetSymbolAddress((void**)&p_xh,  g_xh);
    cudaGetSymbolAddress((void**)&p_xl,  g_xl);
    cudaGetSymbolAddress((void**)&p_wqh, g_wqh);
    cudaGetSymbolAddress((void**)&p_wql, g_wql);
    cudaGetSymbolAddress((void**)&p_wkh, g_wkh);
    cudaGetSymbolAddress((void**)&p_wkl, g_wkl);
    cudaGetSymbolAddress((void**)&p_wvh, g_wvh);
    cudaGetSymbolAddress((void**)&p_wvl, g_wvl);
    cudaGetSymbolAddress((void**)&p_woh, g_woh);
    cudaGetSymbolAddress((void**)&p_wol, g_wol);

    cudaFuncSetAttribute(qkv_tc,
        cudaFuncAttributeMaxDynamicSharedMemorySize, 2 * BUFSZ);
    cudaFuncSetAttribute(proj_tc,
        cudaFuncAttributeMaxDynamicSharedMemorySize, 2 * BUFSZ);
    cudaFuncSetAttribute(attn_tc,
        cudaFuncAttributeMaxDynamicSharedMemorySize, ATT_SMEM);

    split_k<<<XSZ / 1024, 256>>>(x,  p_xh,  p_xl,  XSZ / 4);
    split_k<<<WSZ / 1024, 256>>>(wq, p_wqh, p_wql, WSZ / 4);
    split_k<<<WSZ / 1024, 256>>>(wk, p_wkh, p_wkl, WSZ / 4);
    split_k<<<WSZ / 1024, 256>>>(wv, p_wvh, p_wvl, WSZ / 4);
    split_k<<<WSZ / 1024, 256>>>(wo, p_woh, p_wol, WSZ / 4);

    dim3 gA(18, 64);
    qkv_tc<<<gA, 256, 2 * BUFSZ>>>(cosb, sinb);

    dim3 gB(16, 48);
    attn_tc<<<gB, 256, ATT_SMEM>>>();

    dim3 gC(6, 64);
    proj_tc<<<gC, 256, 2 * BUFSZ>>>(out);
}

// round 8
// speedup vs baseline: 4.8353x; 1.0283x over previous
#include <cuda_runtime.h>
#include <cuda_bf16.h>
#include <cuda_fp16.h>
#include <cstdint>

#define Bn  4
#define Tn  2048
#define DMn 768
#define Hn  12
#define DHn 64
#define QKVSZ (Bn*Hn*Tn*DHn)
#define XSZ   (Bn*Tn*DMn)
#define WSZ   (DMn*DMn)

// Scratch (device globals — no allocation allowed in kernel_launch)
__device__ __align__(16) __nv_bfloat16 g_xh[XSZ],  g_xl[XSZ];
__device__ __align__(16) __nv_bfloat16 g_wqh[WSZ], g_wql[WSZ];
__device__ __align__(16) __nv_bfloat16 g_wkh[WSZ], g_wkl[WSZ];
__device__ __align__(16) __nv_bfloat16 g_wvh[WSZ], g_wvl[WSZ];
__device__ __align__(16) __nv_bfloat16 g_woh[WSZ], g_wol[WSZ];
__device__ __align__(16) __nv_bfloat16 g_qh[QKVSZ], g_ql[QKVSZ];
__device__ __align__(16) __nv_bfloat16 g_kh[QKVSZ], g_kl[QKVSZ];
__device__ __align__(16) __half        g_vh[QKVSZ], g_vl[QKVSZ];
__device__ __align__(16) __nv_bfloat16 g_oh[XSZ],  g_ol[XSZ];

// ===========================================================================
// helpers
// ===========================================================================
__device__ __forceinline__ uint32_t smem_u32(const void* p) {
    uint32_t a;
    asm("{ .reg .u64 t; cvta.to.shared.u64 t, %1; cvt.u32.u64 %0, t; }"
        : "=r"(a) : "l"(p));
    return a;
}

#define SWZ(row, chunk) \
    ((uint32_t)((row) * 64 + ((((chunk) ^ (((row) >> 1) & 3)) & 3) * 16)))

#define SWZA(row, chunk) \
    ((uint32_t)((row) * 128 + ((((chunk) ^ ((row) & 7)) & 7) * 16)))

__device__ __forceinline__ void packhl(float x0, float x1,
                                       uint32_t& h, uint32_t& l) {
    __nv_bfloat16 h0 = __float2bfloat16(x0), h1 = __float2bfloat16(x1);
    float r0 = x0 - __bfloat162float(h0), r1 = x1 - __bfloat162float(h1);
    __nv_bfloat16 l0 = __float2bfloat16(r0), l1 = __float2bfloat16(r1);
    h = (uint32_t)__bfloat16_as_ushort(h0) |
        ((uint32_t)__bfloat16_as_ushort(h1) << 16);
    l = (uint32_t)__bfloat16_as_ushort(l0) |
        ((uint32_t)__bfloat16_as_ushort(l1) << 16);
}

__device__ __forceinline__ void packhl_f16(float x0, float x1,
                                           uint32_t& h, uint32_t& l) {
    float h0 = __half2float(__float2half_rn(x0));
    float h1 = __half2float(__float2half_rn(x1));
    float r0 = x0 - h0, r1 = x1 - h1;
    asm("cvt.rn.f16x2.f32 %0, %1, %2;" : "=r"(h) : "f"(h1), "f"(h0));
    asm("cvt.rn.f16x2.f32 %0, %1, %2;" : "=r"(l) : "f"(r1), "f"(r0));
}

#define CVT_F16X2(res, a, b) \
    asm("cvt.rn.f16x2.f32 %0, %1, %2;" : "=r"(res) : "f"(b), "f"(a))

#define STS4(addr, r0, r1, r2, r3) \
    asm volatile("st.shared.v4.b32 [%0], {%1, %2, %3, %4};" \
        :: "r"(addr), "r"(r0), "r"(r1), "r"(r2), "r"(r3) : "memory")

#define LDSM4(r, addr) \
    asm volatile("ldmatrix.sync.aligned.m8n8.x4.shared.b16 {%0,%1,%2,%3}, [%4];" \
        : "=r"((r)[0]), "=r"((r)[1]), "=r"((r)[2]), "=r"((r)[3]) : "r"(addr))

#define LDSMT4(r, addr) \
    asm volatile("ldmatrix.sync.aligned.m8n8.x4.trans.shared.b16 {%0,%1,%2,%3}, [%4];" \
        : "=r"((r)[0]), "=r"((r)[1]), "=r"((r)[2]), "=r"((r)[3]) : "r"(addr))

#define MMA1(cc, a, b0r, b1r) \
    asm volatile("mma.sync.aligned.m16n8k16.row.col.f32.bf16.bf16.f32 " \
        "{%0,%1,%2,%3}, {%4,%5,%6,%7}, {%8,%9}, {%0,%1,%2,%3};" \
        : "+f"((cc)[0]), "+f"((cc)[1]), "+f"((cc)[2]), "+f"((cc)[3]) \
        : "r"((a)[0]), "r"((a)[1]), "r"((a)[2]), "r"((a)[3]), \
          "r"(b0r), "r"(b1r))

#define MMA1H(cc, a, b0r, b1r) \
    asm volatile("mma.sync.aligned.m16n8k16.row.col.f32.f16.f16.f32 " \
        "{%0,%1,%2,%3}, {%4,%5,%6,%7}, {%8,%9}, {%0,%1,%2,%3};" \
        : "+f"((cc)[0]), "+f"((cc)[1]), "+f"((cc)[2]), "+f"((cc)[3]) \
        : "r"((a)[0]), "r"((a)[1]), "r"((a)[2]), "r"((a)[3]), \
          "r"(b0r), "r"(b1r))

#define CP16(dst, src) \
    asm volatile("cp.async.cg.shared.global [%0], [%1], 16;" \
        :: "r"(dst), "l"(src) : "memory")
#define CPCOMMIT() asm volatile("cp.async.commit_group;" ::: "memory")
#define CPWAIT1()  asm volatile("cp.async.wait_group 1;"  ::: "memory")

// ===========================================================================
// Split kernel: fp32 -> (hi, lo) bf16, elementwise over float4s.
// ===========================================================================
__global__ __launch_bounds__(256) void split_k(
    const float* __restrict__ src, __nv_bfloat16* __restrict__ h,
    __nv_bfloat16* __restrict__ l, int n4)
{
    const int i = blockIdx.x * 256 + threadIdx.x;
    if (i < n4) {
        float4 v = ((const float4*)src)[i];
        uint32_t h0, l0, h1, l1;
        packhl(v.x, v.y, h0, l0);
        packhl(v.z, v.w, h1, l1);
        ((uint2*)h)[i] = make_uint2(h0, h1);
        ((uint2*)l)[i] = make_uint2(l0, l1);
    }
}

// ===========================================================================
// GEMM core (pre-split bf16, cp.async 3-stage ring). 128x128 C, BK=32,
// 8 warps, 3 MMA terms. Buffer = Ah,Al,Bh,Bl 128x32 bf16 (8KB each) = 32KB.
// ===========================================================================
#define OFF_AH 0
#define OFF_AL 8192
#define OFF_BH 16384
#define OFF_BL 24576
#define BUFSZ  32768
#define NSTAGE 3
#define KSTAGES 24

#define MMA_ALL(AF, BF) \
    _Pragma("unroll") \
    for (int mt = 0; mt < 2; mt++) \
        _Pragma("unroll") \
        for (int nt = 0; nt < 8; nt++) \
            MMA1(c[mt][nt], (AF)[mt], (BF)[nt >> 1][(nt & 1) * 2], \
                 (BF)[nt >> 1][(nt & 1) * 2 + 1]);

#define COMP_KB(kb, SBASE) do {                                               \
    uint32_t aF[2][4], bF[4][4], aT[2][4], bT[4][4];                          \
    _Pragma("unroll")                                                         \
    for (int mt = 0; mt < 2; mt++)                                            \
        LDSM4(aF[mt], (SBASE) + OFF_AH +                                      \
              SWZ(mw * 32 + mt * 16 + a_r, (kb) * 2 + a_cb));                 \
    _Pragma("unroll")                                                         \
    for (int np = 0; np < 4; np++)                                            \
        LDSM4(bF[np], (SBASE) + OFF_BH +                                      \
              SWZ(nw * 64 + np * 16 + b_off, (kb) * 2 + b_cb));               \
    MMA_ALL(aF, bF);                                                          \
    _Pragma("unroll")                                                         \
    for (int mt = 0; mt < 2; mt++)                                            \
        LDSM4(aT[mt], (SBASE) + OFF_AL +                                      \
              SWZ(mw * 32 + mt * 16 + a_r, (kb) * 2 + a_cb));                 \
    MMA_ALL(aT, bF);                                                          \
    _Pragma("unroll")                                                         \
    for (int np = 0; np < 4; np++)                                            \
        LDSM4(bT[np], (SBASE) + OFF_BL +                                      \
              SWZ(nw * 64 + np * 16 + b_off, (kb) * 2 + b_cb));               \
    MMA_ALL(aF, bT);                                                          \
} while (0)

#define GEMM_SETUP()                                                          \
    extern __shared__ unsigned char dynsm[];                                  \
    const uint32_t sbase = smem_u32(dynsm);                                   \
    const int tid = threadIdx.x, lane = tid & 31, wid = tid >> 5;             \
    const int mw = wid & 3, nw = wid >> 2;                                    \
    const int a_r = lane & 15, a_cb = lane >> 4;                              \
    const int b_off = ((lane >> 4) << 3) + (lane & 7), b_cb = (lane >> 3) & 1;\
    const int ldrow = tid >> 1, ldhalf = tid & 1;                             \
    float c[2][8][4];                                                         \
    _Pragma("unroll")                                                         \
    for (int i = 0; i < 2; i++)                                               \
        _Pragma("unroll")                                                     \
        for (int j = 0; j < 8; j++)                                           \
            _Pragma("unroll")                                                 \
            for (int q = 0; q < 4; q++) c[i][j][q] = 0.f;

// issue one stage's loads: 8x 16B cp.async per thread, then commit
#define GEMM_CPA(s, bb)                                                       \
    {                                                                         \
        const size_t ro = (size_t)ldrow * DMn + (s) * 32 + ldhalf * 16;       \
        const uint32_t o0 = SWZ(ldrow, ldhalf * 2);                           \
        const uint32_t o1 = SWZ(ldrow, ldhalf * 2 + 1);                       \
        CP16((bb) + OFF_AH + o0, gAh + ro);                                   \
        CP16((bb) + OFF_AH + o1, gAh + ro + 8);                               \
        CP16((bb) + OFF_AL + o0, gAl + ro);                                   \
        CP16((bb) + OFF_AL + o1, gAl + ro + 8);                               \
        CP16((bb) + OFF_BH + o0, gBh + ro);                                   \
        CP16((bb) + OFF_BH + o1, gBh + ro + 8);                               \
        CP16((bb) + OFF_BL + o0, gBl + ro);                                   \
        CP16((bb) + OFF_BL + o1, gBl + ro + 8);                               \
        CPCOMMIT();                                                           \
    }

#define GEMM_MAINLOOP()                                                       \
    GEMM_CPA(0, sbase);                                                       \
    GEMM_CPA(1, sbase + BUFSZ);                                               \
    _Pragma("unroll 1")                                                       \
    for (int s = 0; s < KSTAGES; s++) {                                       \
        CPWAIT1();                                                            \
        __syncthreads();                                                      \
        const uint32_t cur = sbase + (uint32_t)(s % NSTAGE) * BUFSZ;          \
        COMP_KB(0, cur);                                                      \
        COMP_KB(1, cur);                                                      \
        if (s + 2 < KSTAGES)                                                  \
            GEMM_CPA(s + 2, sbase + (uint32_t)((s + 2) % NSTAGE) * BUFSZ);    \
    }

// ===========================================================================
// Kernel A: QKV GEMM + RoPE; writes split Q/K (bf16) and split V (fp16).
// grid (18, 64): x = mat*6 + ntile, y = mtile.
// ===========================================================================
__global__ __launch_bounds__(256, 1) void qkv_tc(
    const float* __restrict__ cosb, const float* __restrict__ sinb)
{
    GEMM_SETUP();
    const int mat = blockIdx.x / 6, ntm = blockIdx.x % 6;
    const int m0 = blockIdx.y * 128, n0 = ntm * 128;
    const __nv_bfloat16* gAh = g_xh + (size_t)m0 * DMn;
    const __nv_bfloat16* gAl = g_xl + (size_t)m0 * DMn;
    const __nv_bfloat16* gBh = ((mat == 0) ? g_wqh : (mat == 1) ? g_wkh : g_wvh)
                               + (size_t)n0 * DMn;
    const __nv_bfloat16* gBl = ((mat == 0) ? g_wql : (mat == 1) ? g_wkl : g_wvl)
                               + (size_t)n0 * DMn;

    GEMM_MAINLOOP();

    #pragma unroll
    for (int mt = 0; mt < 2; mt++) {
        const int r0 = m0 + mw * 32 + mt * 16 + (lane >> 2);
        #pragma unroll
        for (int half = 0; half < 2; half++) {
            const int m = r0 + half * 8;
            const int b = m >> 11, tt = m & 2047;
            #pragma unroll
            for (int nt = 0; nt < 8; nt++) {
                const int colN = n0 + nw * 64 + nt * 8 + (lane & 3) * 2;
                const int head = colN >> 6, dh = colN & 63, pi = dh >> 1;
                float v0 = c[mt][nt][half * 2 + 0];
                float v1 = c[mt][nt][half * 2 + 1];
                const size_t idx =
                    ((size_t)(b * Hn + head) * Tn + tt) * DHn + dh;
                uint32_t hh, ll;
                if (mat < 2) {
                    float cs = cosb[tt * 32 + pi], sn = sinb[tt * 32 + pi];
                    float o0 = v0 * cs - v1 * sn;
                    float o1 = v0 * sn + v1 * cs;
                    packhl(o0, o1, hh, ll);
                    if (mat == 0) {
                        *(uint32_t*)(g_qh + idx) = hh;
                        *(uint32_t*)(g_ql + idx) = ll;
                    } else {
                        *(uint32_t*)(g_kh + idx) = hh;
                        *(uint32_t*)(g_kl + idx) = ll;
                    }
                } else {
                    packhl_f16(v0, v1, hh, ll);
                    *(uint32_t*)(g_vh + idx) = hh;
                    *(uint32_t*)(g_vl + idx) = ll;
                }
            }
        }
    }
}

// ===========================================================================
// Kernel C: output projection; A = split O, B = split wo; fp32 out.
// ===========================================================================
__global__ __launch_bounds__(256, 1) void proj_tc(float* __restrict__ out)
{
    GEMM_SETUP();
    const int m0 = blockIdx.y * 128, n0 = blockIdx.x * 128;
    const __nv_bfloat16* gAh = g_oh + (size_t)m0 * DMn;
    const __nv_bfloat16* gAl = g_ol + (size_t)m0 * DMn;
    const __nv_bfloat16* gBh = g_woh + (size_t)n0 * DMn;
    const __nv_bfloat16* gBl = g_wol + (size_t)n0 * DMn;

    GEMM_MAINLOOP();

    #pragma unroll
    for (int mt = 0; mt < 2; mt++) {
        const int r0 = m0 + mw * 32 + mt * 16 + (lane >> 2);
        #pragma unroll
        for (int half = 0; half < 2; half++) {
            const int m = r0 + half * 8;
            #pragma unroll
            for (int nt = 0; nt < 8; nt++) {
                const int colN = n0 + nw * 64 + nt * 8 + (lane & 3) * 2;
                *(float2*)(out + (size_t)m * DMn + colN) =
                    make_float2(c[mt][nt][half * 2], c[mt][nt][half * 2 + 1]);
            }
        }
    }
}

// ===========================================================================
// Kernel B: causal flash attention via HMMA (pre-split inputs). Unchanged.
// ===========================================================================
#define AQ_H 0
#define AQ_L 16384
#define AK_H 32768
#define AK_L 40960
#define AV_H 49152
#define AV_L 57344
#define ATT_SMEM 65536

__global__ __launch_bounds__(256, 1) void attn_tc()
{
    extern __shared__ unsigned char dynsm[];
    const uint32_t sb = smem_u32(dynsm);
    const int tid = threadIdx.x, lane = tid & 31, mw = tid >> 5;
    const int qt = 15 - (int)blockIdx.x;
    const int bh = blockIdx.y;
    const int q0 = qt * 128;
    const int b_off = ((lane >> 4) << 3) + (lane & 7);
    const int b_cb  = (lane >> 3) & 1;

    {
        const int row = tid >> 1, half = tid & 1;
        const size_t go = ((size_t)bh * Tn + q0 + row) * DHn + half * 32;
        const uint4* ph = (const uint4*)(g_qh + go);
        const uint4* pl = (const uint4*)(g_ql + go);
        #pragma unroll
        for (int c4 = 0; c4 < 4; c4++) {
            const uint32_t o = SWZA(row, half * 4 + c4);
            uint4 vh = ph[c4], vl = pl[c4];
            STS4(sb + AQ_H + o, vh.x, vh.y, vh.z, vh.w);
            STS4(sb + AQ_L + o, vl.x, vl.y, vl.z, vl.w);
        }
    }
    __syncthreads();

    uint32_t aQh[4][4], aQl[4][4];
    #pragma unroll
    for (int kc = 0; kc < 4; kc++) {
        const uint32_t o = SWZA(mw * 16 + (lane & 15), kc * 2 + (lane >> 4));
        LDSM4(aQh[kc], sb + AQ_H + o);
        LDSM4(aQl[kc], sb + AQ_L + o);
    }

    float co[8][4];
    #pragma unroll
    for (int i = 0; i < 8; i++)
        #pragma unroll
        for (int j = 0; j < 4; j++) co[i][j] = 0.f;
    float m0 = -1e30f, m1 = -1e30f, l0 = 0.f, l1 = 0.f;
    const int rowq = q0 + mw * 16 + (lane >> 2);
    const int nkt = 2 * qt + 2;

    for (int kt = 0; kt < nkt; kt++) {
        const int krow = tid >> 2, kq = tid & 3;
        const size_t go = ((size_t)bh * Tn + kt * 64 + krow) * DHn + kq * 16;
        uint4 vkh[2], vkl[2], vvh[2], vvl[2];
        { const uint4* p = (const uint4*)(g_kh + go); vkh[0]=p[0]; vkh[1]=p[1]; }
        { const uint4* p = (const uint4*)(g_kl + go); vkl[0]=p[0]; vkl[1]=p[1]; }
        { const uint4* p = (const uint4*)(g_vh + go); vvh[0]=p[0]; vvh[1]=p[1]; }
        { const uint4* p = (const uint4*)(g_vl + go); vvl[0]=p[0]; vvl[1]=p[1]; }
        __syncthreads();
        {
            const uint32_t o0 = SWZA(krow, kq * 2), o1 = SWZA(krow, kq * 2 + 1);
            STS4(sb + AK_H + o0, vkh[0].x, vkh[0].y, vkh[0].z, vkh[0].w);
            STS4(sb + AK_H + o1, vkh[1].x, vkh[1].y, vkh[1].z, vkh[1].w);
            STS4(sb + AK_L + o0, vkl[0].x, vkl[0].y, vkl[0].z, vkl[0].w);
            STS4(sb + AK_L + o1, vkl[1].x, vkl[1].y, vkl[1].z, vkl[1].w);
            STS4(sb + AV_H + o0, vvh[0].x, vvh[0].y, vvh[0].z, vvh[0].w);
            STS4(sb + AV_H + o1, vvh[1].x, vvh[1].y, vvh[1].z, vvh[1].w);
            STS4(sb + AV_L + o0, vvl[0].x, vvl[0].y, vvl[0].z, vvl[0].w);
            STS4(sb + AV_L + o1, vvl[1].x, vvl[1].y, vvl[1].z, vvl[1].w);
        }
        __syncthreads();

        float cs[8][4];
        #pragma unroll
        for (int i = 0; i < 8; i++)
            #pragma unroll
            for (int j = 0; j < 4; j++) cs[i][j] = 0.f;
        #pragma unroll
        for (int kc = 0; kc < 4; kc++) {
            uint32_t bKh[4][4], bKl[4][4];
            #pragma unroll
            for (int np = 0; np < 4; np++)
                LDSM4(bKh[np], sb + AK_H +
                      SWZA(np * 16 + b_off, kc * 2 + b_cb));
            #pragma unroll
            for (int nt = 0; nt < 8; nt++)
                MMA1(cs[nt], aQh[kc], bKh[nt>>1][(nt&1)*2],
                     bKh[nt>>1][(nt&1)*2+1]);
            #pragma unroll
            for (int nt = 0; nt < 8; nt++)
                MMA1(cs[nt], aQl[kc], bKh[nt>>1][(nt&1)*2],
                     bKh[nt>>1][(nt&1)*2+1]);
            #pragma unroll
            for (int np = 0; np < 4; np++)
                LDSM4(bKl[np], sb + AK_L +
                      SWZA(np * 16 + b_off, kc * 2 + b_cb));
            #pragma unroll
            for (int nt = 0; nt < 8; nt++)
                MMA1(cs[nt], aQh[kc], bKl[nt>>1][(nt&1)*2],
                     bKl[nt>>1][(nt&1)*2+1]);
        }

        const bool domask = (kt >= 2 * qt);
        float mt0 = -1e30f, mt1 = -1e30f;
        #pragma unroll
        for (int nt = 0; nt < 8; nt++) {
            const int ck = kt * 64 + nt * 8 + (lane & 3) * 2;
            float s0 = cs[nt][0] * 0.125f, s1 = cs[nt][1] * 0.125f;
            float s2 = cs[nt][2] * 0.125f, s3 = cs[nt][3] * 0.125f;
            if (domask) {
                if (ck     > rowq)     s0 = -1e30f;
                if (ck + 1 > rowq)     s1 = -1e30f;
                if (ck     > rowq + 8) s2 = -1e30f;
                if (ck + 1 > rowq + 8) s3 = -1e30f;
            }
            cs[nt][0] = s0; cs[nt][1] = s1; cs[nt][2] = s2; cs[nt][3] = s3;
            mt0 = fmaxf(mt0, fmaxf(s0, s1));
            mt1 = fmaxf(mt1, fmaxf(s2, s3));
        }
        mt0 = fmaxf(mt0, __shfl_xor_sync(0xffffffffu, mt0, 1));
        mt0 = fmaxf(mt0, __shfl_xor_sync(0xffffffffu, mt0, 2));
        mt1 = fmaxf(mt1, __shfl_xor_sync(0xffffffffu, mt1, 1));
        mt1 = fmaxf(mt1, __shfl_xor_sync(0xffffffffu, mt1, 2));
        const float nm0 = fmaxf(m0, mt0), nm1 = fmaxf(m1, mt1);
        const float cr0 = __expf(m0 - nm0), cr1 = __expf(m1 - nm1);
        m0 = nm0; m1 = nm1; l0 *= cr0; l1 *= cr1;

        uint32_t aP[4][4];
        #pragma unroll
        for (int nt = 0; nt < 8; nt++) {
            float p0 = __expf(cs[nt][0] - m0), p1 = __expf(cs[nt][1] - m0);
            float p2 = __expf(cs[nt][2] - m1), p3 = __expf(cs[nt][3] - m1);
            l0 += p0 + p1; l1 += p2 + p3;
            CVT_F16X2(aP[nt >> 1][(nt & 1) * 2],     p0, p1);
            CVT_F16X2(aP[nt >> 1][(nt & 1) * 2 + 1], p2, p3);
        }
        #pragma unroll
        for (int nt = 0; nt < 8; nt++) {
            co[nt][0] *= cr0; co[nt][1] *= cr0;
            co[nt][2] *= cr1; co[nt][3] *= cr1;
        }

        #pragma unroll
        for (int kc = 0; kc < 4; kc++) {
            uint32_t bVh[4][4], bVl[4][4];
            const uint32_t vrow = kc * 16 + ((lane >> 3) & 1) * 8 + (lane & 7);
            #pragma unroll
            for (int g = 0; g < 4; g++)
                LDSMT4(bVh[g], sb + AV_H + SWZA(vrow, 2 * g + (lane >> 4)));
            #pragma unroll
            for (int nt = 0; nt < 8; nt++)
                MMA1H(co[nt], aP[kc], bVh[nt>>1][(nt&1)*2],
                      bVh[nt>>1][(nt&1)*2+1]);
            #pragma unroll
            for (int g = 0; g < 4; g++)
                LDSMT4(bVl[g], sb + AV_L + SWZA(vrow, 2 * g + (lane >> 4)));
            #pragma unroll
            for (int nt = 0; nt < 8; nt++)
                MMA1H(co[nt], aP[kc], bVl[nt>>1][(nt&1)*2],
                      bVl[nt>>1][(nt&1)*2+1]);
        }
    }

    l0 += __shfl_xor_sync(0xffffffffu, l0, 1);
    l0 += __shfl_xor_sync(0xffffffffu, l0, 2);
    l1 += __shfl_xor_sync(0xffffffffu, l1, 1);
    l1 += __shfl_xor_sync(0xffffffffu, l1, 2);
    const float i0 = 1.f / l0, i1 = 1.f / l1;
    const int b = bh / Hn, h = bh % Hn;
    const int t0 = q0 + mw * 16 + (lane >> 2);
    const size_t base0 = (size_t)(b * Tn + t0)     * DMn + h * DHn;
    const size_t base1 = (size_t)(b * Tn + t0 + 8) * DMn + h * DHn;
    #pragma unroll
    for (int nt = 0; nt < 8; nt++) {
        const int dh = nt * 8 + (lane & 3) * 2;
        uint32_t hh, ll;
        packhl(co[nt][0] * i0, co[nt][1] * i0, hh, ll);
        *(uint32_t*)(g_oh + base0 + dh) = hh;
        *(uint32_t*)(g_ol + base0 + dh) = ll;
        packhl(co[nt][2] * i1, co[nt][3] * i1, hh, ll);
        *(uint32_t*)(g_oh + base1 + dh) = hh;
        *(uint32_t*)(g_ol + base1 + dh) = ll;
    }
}

// ---------------------------------------------------------------------------
extern "C" void kernel_launch(void* const* d_in, const int* in_sizes, int n_in,
                              void* d_out, int out_size)
{
    const float* x    = (const float*)d_in[0];
    const float* cosb = (const float*)d_in[1];
    const float* sinb = (const float*)d_in[2];
    const float* wq   = (const float*)d_in[3];
    const float* wk   = (const float*)d_in[4];
    const float* wv   = (const float*)d_in[5];
    const float* wo   = (const float*)d_in[6];
    float* out = (float*)d_out;

    __nv_bfloat16 *p_xh, *p_xl, *p_wqh, *p_wql, *p_wkh, *p_wkl;
    __nv_bfloat16 *p_wvh, *p_wvl, *p_woh, *p_wol;
    cudaGetSymbolAddress((void**)&p_xh,  g_xh);
    cudaGetSymbolAddress((void**)&p_xl,  g_xl);
    cudaGetSymbolAddress((void**)&p_wqh, g_wqh);
    cudaGetSymbolAddress((void**)&p_wql, g_wql);
    cudaGetSymbolAddress((void**)&p_wkh, g_wkh);
    cudaGetSymbolAddress((void**)&p_wkl, g_wkl);
    cudaGetSymbolAddress((void**)&p_wvh, g_wvh);
    cudaGetSymbolAddress((void**)&p_wvl, g_wvl);
    cudaGetSymbolAddress((void**)&p_woh, g_woh);
    cudaGetSymbolAddress((void**)&p_wol, g_wol);

    cudaFuncSetAttribute(qkv_tc,
        cudaFuncAttributeMaxDynamicSharedMemorySize, NSTAGE * BUFSZ);
    cudaFuncSetAttribute(proj_tc,
        cudaFuncAttributeMaxDynamicSharedMemorySize, NSTAGE * BUFSZ);
    cudaFuncSetAttribute(attn_tc,
        cudaFuncAttributeMaxDynamicSharedMemorySize, ATT_SMEM);

    split_k<<<XSZ / 1024, 256>>>(x,  p_xh,  p_xl,  XSZ / 4);
    split_k<<<WSZ / 1024, 256>>>(wq, p_wqh, p_wql, WSZ / 4);
    split_k<<<WSZ / 1024, 256>>>(wk, p_wkh, p_wkl, WSZ / 4);
    split_k<<<WSZ / 1024, 256>>>(wv, p_wvh, p_wvl, WSZ / 4);
    split_k<<<WSZ / 1024, 256>>>(wo, p_woh, p_wol, WSZ / 4);

    dim3 gA(18, 64);
    qkv_tc<<<gA, 256, NSTAGE * BUFSZ>>>(cosb, sinb);

    dim3 gB(16, 48);
    attn_tc<<<gB, 256, ATT_SMEM>>>();

    dim3 gC(6, 64);
    proj_tc<<<gC, 256, NSTAGE * BUFSZ>>>(out);
}

// round 9
// speedup vs baseline: 5.4918x; 1.1358x over previous
#include <cuda_runtime.h>
#include <cuda_bf16.h>
#include <cuda_fp16.h>
#include <cstdint>

#define Bn  4
#define Tn  2048
#define DMn 768
#define Hn  12
#define DHn 64
#define QKVSZ (Bn*Hn*Tn*DHn)
#define XSZ   (Bn*Tn*DMn)
#define WSZ   (DMn*DMn)

// Scratch (device globals — no allocation allowed in kernel_launch)
__device__ __align__(16) __nv_bfloat16 g_xh[XSZ],  g_xl[XSZ];
__device__ __align__(16) __nv_bfloat16 g_wqh[WSZ], g_wql[WSZ];
__device__ __align__(16) __nv_bfloat16 g_wkh[WSZ], g_wkl[WSZ];
__device__ __align__(16) __nv_bfloat16 g_wvh[WSZ], g_wvl[WSZ];
__device__ __align__(16) __nv_bfloat16 g_woh[WSZ], g_wol[WSZ];
__device__ __align__(16) __nv_bfloat16 g_qh[QKVSZ], g_ql[QKVSZ];
__device__ __align__(16) __nv_bfloat16 g_kh[QKVSZ], g_kl[QKVSZ];
__device__ __align__(16) __half        g_vh[QKVSZ];
__device__ __align__(16) __nv_bfloat16 g_oh[XSZ],  g_ol[XSZ];

// ===========================================================================
// helpers
// ===========================================================================
__device__ __forceinline__ uint32_t smem_u32(const void* p) {
    uint32_t a;
    asm("{ .reg .u64 t; cvta.to.shared.u64 t, %1; cvt.u32.u64 %0, t; }"
        : "=r"(a) : "l"(p));
    return a;
}

#define SWZ(row, chunk) \
    ((uint32_t)((row) * 64 + ((((chunk) ^ (((row) >> 1) & 3)) & 3) * 16)))

#define SWZA(row, chunk) \
    ((uint32_t)((row) * 128 + ((((chunk) ^ ((row) & 7)) & 7) * 16)))

__device__ __forceinline__ void packhl(float x0, float x1,
                                       uint32_t& h, uint32_t& l) {
    __nv_bfloat16 h0 = __float2bfloat16(x0), h1 = __float2bfloat16(x1);
    float r0 = x0 - __bfloat162float(h0), r1 = x1 - __bfloat162float(h1);
    __nv_bfloat16 l0 = __float2bfloat16(r0), l1 = __float2bfloat16(r1);
    h = (uint32_t)__bfloat16_as_ushort(h0) |
        ((uint32_t)__bfloat16_as_ushort(h1) << 16);
    l = (uint32_t)__bfloat16_as_ushort(l0) |
        ((uint32_t)__bfloat16_as_ushort(l1) << 16);
}

#define CVT_F16X2(res, a, b) \
    asm("cvt.rn.f16x2.f32 %0, %1, %2;" : "=r"(res) : "f"(b), "f"(a))

#define STS4(addr, r0, r1, r2, r3) \
    asm volatile("st.shared.v4.b32 [%0], {%1, %2, %3, %4};" \
        :: "r"(addr), "r"(r0), "r"(r1), "r"(r2), "r"(r3) : "memory")

#define LDSM4(r, addr) \
    asm volatile("ldmatrix.sync.aligned.m8n8.x4.shared.b16 {%0,%1,%2,%3}, [%4];" \
        : "=r"((r)[0]), "=r"((r)[1]), "=r"((r)[2]), "=r"((r)[3]) : "r"(addr))

#define LDSMT4(r, addr) \
    asm volatile("ldmatrix.sync.aligned.m8n8.x4.trans.shared.b16 {%0,%1,%2,%3}, [%4];" \
        : "=r"((r)[0]), "=r"((r)[1]), "=r"((r)[2]), "=r"((r)[3]) : "r"(addr))

#define MMA1(cc, a, b0r, b1r) \
    asm volatile("mma.sync.aligned.m16n8k16.row.col.f32.bf16.bf16.f32 " \
        "{%0,%1,%2,%3}, {%4,%5,%6,%7}, {%8,%9}, {%0,%1,%2,%3};" \
        : "+f"((cc)[0]), "+f"((cc)[1]), "+f"((cc)[2]), "+f"((cc)[3]) \
        : "r"((a)[0]), "r"((a)[1]), "r"((a)[2]), "r"((a)[3]), \
          "r"(b0r), "r"(b1r))

#define MMA1H(cc, a, b0r, b1r) \
    asm volatile("mma.sync.aligned.m16n8k16.row.col.f32.f16.f16.f32 " \
        "{%0,%1,%2,%3}, {%4,%5,%6,%7}, {%8,%9}, {%0,%1,%2,%3};" \
        : "+f"((cc)[0]), "+f"((cc)[1]), "+f"((cc)[2]), "+f"((cc)[3]) \
        : "r"((a)[0]), "r"((a)[1]), "r"((a)[2]), "r"((a)[3]), \
          "r"(b0r), "r"(b1r))

#define CP16(dst, src) \
    asm volatile("cp.async.cg.shared.global [%0], [%1], 16;" \
        :: "r"(dst), "l"(src) : "memory")
#define CPCOMMIT() asm volatile("cp.async.commit_group;" ::: "memory")
#define CPWAIT1()  asm volatile("cp.async.wait_group 1;"  ::: "memory")

// ===========================================================================
// Merged split kernel: fp32 -> (hi, lo) bf16 for x, wq, wk, wv, wo.
// ===========================================================================
#define X4  (XSZ/4)
#define W4  (WSZ/4)

__global__ __launch_bounds__(256) void split_all(
    const float* __restrict__ x,  const float* __restrict__ wq,
    const float* __restrict__ wk, const float* __restrict__ wv,
    const float* __restrict__ wo)
{
    int i = blockIdx.x * 256 + threadIdx.x;
    const float* src; __nv_bfloat16 *h, *l;
    if (i < X4)                { src = x;  h = g_xh;  l = g_xl;  }
    else if ((i -= X4) < W4)   { src = wq; h = g_wqh; l = g_wql; }
    else if ((i -= W4) < W4)   { src = wk; h = g_wkh; l = g_wkl; }
    else if ((i -= W4) < W4)   { src = wv; h = g_wvh; l = g_wvl; }
    else if ((i -= W4) < W4)   { src = wo; h = g_woh; l = g_wol; }
    else return;
    float4 v = ((const float4*)src)[i];
    uint32_t h0, l0, h1, l1;
    packhl(v.x, v.y, h0, l0);
    packhl(v.z, v.w, h1, l1);
    ((uint2*)h)[i] = make_uint2(h0, h1);
    ((uint2*)l)[i] = make_uint2(l0, l1);
}

// ===========================================================================
// GEMM core: 128x64 C tile, BK=32, 8 warps (warp 32x32), 3 MMA terms,
// cp.async 3-stage ring. Buffer: Ah/Al 8KB + Bh/Bl 4KB = 24KB.
// 2 CTAs/SM (launch_bounds(256,2), 3*24KB*2 = 144KB smem).
// ===========================================================================
#define OFF_AH 0
#define OFF_AL 8192
#define OFF_BH 16384
#define OFF_BL 20480
#define BUFSZ  24576
#define NSTAGE 3
#define KSTAGES 24

#define MMA_ALL(AF, BF) \
    _Pragma("unroll") \
    for (int mt = 0; mt < 2; mt++) \
        _Pragma("unroll") \
        for (int nt = 0; nt < 4; nt++) \
            MMA1(c[mt][nt], (AF)[mt], (BF)[nt >> 1][(nt & 1) * 2], \
                 (BF)[nt >> 1][(nt & 1) * 2 + 1]);

#define COMP_KB(kb, SBASE) do {                                               \
    uint32_t aF[2][4], bF[2][4], aT[2][4], bT[2][4];                          \
    _Pragma("unroll")                                                         \
    for (int mt = 0; mt < 2; mt++)                                            \
        LDSM4(aF[mt], (SBASE) + OFF_AH +                                      \
              SWZ(mw * 32 + mt * 16 + a_r, (kb) * 2 + a_cb));                 \
    _Pragma("unroll")                                                         \
    for (int np = 0; np < 2; np++)                                            \
        LDSM4(bF[np], (SBASE) + OFF_BH +                                      \
              SWZ(nw * 32 + np * 16 + b_off, (kb) * 2 + b_cb));               \
    MMA_ALL(aF, bF);                                                          \
    _Pragma("unroll")                                                         \
    for (int mt = 0; mt < 2; mt++)                                            \
        LDSM4(aT[mt], (SBASE) + OFF_AL +                                      \
              SWZ(mw * 32 + mt * 16 + a_r, (kb) * 2 + a_cb));                 \
    MMA_ALL(aT, bF);                                                          \
    _Pragma("unroll")                                                         \
    for (int np = 0; np < 2; np++)                                            \
        LDSM4(bT[np], (SBASE) + OFF_BL +                                      \
              SWZ(nw * 32 + np * 16 + b_off, (kb) * 2 + b_cb));               \
    MMA_ALL(aF, bT);                                                          \
} while (0)

#define GEMM_SETUP()                                                          \
    extern __shared__ unsigned char dynsm[];                                  \
    const uint32_t sbase = smem_u32(dynsm);                                   \
    const int tid = threadIdx.x, lane = tid & 31, wid = tid >> 5;             \
    const int mw = wid & 3, nw = wid >> 2;                                    \
    const int a_r = lane & 15, a_cb = lane >> 4;                              \
    const int b_off = ((lane >> 4) << 3) + (lane & 7), b_cb = (lane >> 3) & 1;\
    const int ldrow = tid >> 1, ldhalf = tid & 1;                             \
    const int brow = tid >> 2, bch = tid & 3;                                 \
    float c[2][4][4];                                                         \
    _Pragma("unroll")                                                         \
    for (int i = 0; i < 2; i++)                                               \
        _Pragma("unroll")                                                     \
        for (int j = 0; j < 4; j++)                                           \
            _Pragma("unroll")                                                 \
            for (int q = 0; q < 4; q++) c[i][j][q] = 0.f;

// A: 128 rows x 2 chunks/thread; B: 64 rows x 1 chunk/thread. 6 CP16/thread.
#define GEMM_CPA(s, bb)                                                       \
    {                                                                         \
        const size_t ro = (size_t)ldrow * DMn + (s) * 32 + ldhalf * 16;       \
        const uint32_t o0 = SWZ(ldrow, ldhalf * 2);                           \
        const uint32_t o1 = SWZ(ldrow, ldhalf * 2 + 1);                       \
        CP16((bb) + OFF_AH + o0, gAh + ro);                                   \
        CP16((bb) + OFF_AH + o1, gAh + ro + 8);                               \
        CP16((bb) + OFF_AL + o0, gAl + ro);                                   \
        CP16((bb) + OFF_AL + o1, gAl + ro + 8);                               \
        const size_t rb = (size_t)brow * DMn + (s) * 32 + bch * 8;            \
        const uint32_t ob = SWZ(brow, bch);                                   \
        CP16((bb) + OFF_BH + ob, gBh + rb);                                   \
        CP16((bb) + OFF_BL + ob, gBl + rb);                                   \
        CPCOMMIT();                                                           \
    }

#define GEMM_MAINLOOP()                                                       \
    GEMM_CPA(0, sbase);                                                       \
    GEMM_CPA(1, sbase + BUFSZ);                                               \
    _Pragma("unroll 1")                                                       \
    for (int s = 0; s < KSTAGES; s++) {                                       \
        CPWAIT1();                                                            \
        __syncthreads();                                                      \
        const uint32_t cur = sbase + (uint32_t)(s % NSTAGE) * BUFSZ;          \
        COMP_KB(0, cur);                                                      \
        COMP_KB(1, cur);                                                      \
        if (s + 2 < KSTAGES)                                                  \
            GEMM_CPA(s + 2, sbase + (uint32_t)((s + 2) % NSTAGE) * BUFSZ);    \
    }

// ===========================================================================
// Kernel A: QKV GEMM + RoPE; writes split Q/K (bf16), V (fp16 hi only).
// grid (36, 64): x = mat*12 + ntile(64), y = mtile(128).
// ===========================================================================
__global__ __launch_bounds__(256, 2) void qkv_tc(
    const float* __restrict__ cosb, const float* __restrict__ sinb)
{
    GEMM_SETUP();
    const int mat = blockIdx.x / 12, ntm = blockIdx.x % 12;
    const int m0 = blockIdx.y * 128, n0 = ntm * 64;
    const __nv_bfloat16* gAh = g_xh + (size_t)m0 * DMn;
    const __nv_bfloat16* gAl = g_xl + (size_t)m0 * DMn;
    const __nv_bfloat16* gBh = ((mat == 0) ? g_wqh : (mat == 1) ? g_wkh : g_wvh)
                               + (size_t)n0 * DMn;
    const __nv_bfloat16* gBl = ((mat == 0) ? g_wql : (mat == 1) ? g_wkl : g_wvl)
                               + (size_t)n0 * DMn;

    GEMM_MAINLOOP();

    const int head = ntm;   // n-tile == head (64 cols)
    #pragma unroll
    for (int mt = 0; mt < 2; mt++) {
        const int r0 = m0 + mw * 32 + mt * 16 + (lane >> 2);
        #pragma unroll
        for (int half = 0; half < 2; half++) {
            const int m = r0 + half * 8;
            const int b = m >> 11, tt = m & 2047;
            #pragma unroll
            for (int nt = 0; nt < 4; nt++) {
                const int dh = nw * 32 + nt * 8 + (lane & 3) * 2;
                const int pi = dh >> 1;
                float v0 = c[mt][nt][half * 2 + 0];
                float v1 = c[mt][nt][half * 2 + 1];
                const size_t idx =
                    ((size_t)(b * Hn + head) * Tn + tt) * DHn + dh;
                uint32_t hh, ll;
                if (mat < 2) {
                    float cs = cosb[tt * 32 + pi], sn = sinb[tt * 32 + pi];
                    float o0 = v0 * cs - v1 * sn;
                    float o1 = v0 * sn + v1 * cs;
                    packhl(o0, o1, hh, ll);
                    if (mat == 0) {
                        *(uint32_t*)(g_qh + idx) = hh;
                        *(uint32_t*)(g_ql + idx) = ll;
                    } else {
                        *(uint32_t*)(g_kh + idx) = hh;
                        *(uint32_t*)(g_kl + idx) = ll;
                    }
                } else {
                    CVT_F16X2(hh, v0, v1);
                    *(uint32_t*)(g_vh + idx) = hh;
                }
            }
        }
    }
}

// ===========================================================================
// Kernel C: output projection; grid (12, 64); fp32 out.
// ===========================================================================
__global__ __launch_bounds__(256, 2) void proj_tc(float* __restrict__ out)
{
    GEMM_SETUP();
    const int m0 = blockIdx.y * 128, n0 = blockIdx.x * 64;
    const __nv_bfloat16* gAh = g_oh + (size_t)m0 * DMn;
    const __nv_bfloat16* gAl = g_ol + (size_t)m0 * DMn;
    const __nv_bfloat16* gBh = g_woh + (size_t)n0 * DMn;
    const __nv_bfloat16* gBl = g_wol + (size_t)n0 * DMn;

    GEMM_MAINLOOP();

    #pragma unroll
    for (int mt = 0; mt < 2; mt++) {
        const int r0 = m0 + mw * 32 + mt * 16 + (lane >> 2);
        #pragma unroll
        for (int half = 0; half < 2; half++) {
            const int m = r0 + half * 8;
            #pragma unroll
            for (int nt = 0; nt < 4; nt++) {
                const int colN = n0 + nw * 32 + nt * 8 + (lane & 3) * 2;
                *(float2*)(out + (size_t)m * DMn + colN) =
                    make_float2(c[mt][nt][half * 2], c[mt][nt][half * 2 + 1]);
            }
        }
    }
}

// ===========================================================================
// Kernel B: causal flash attention via HMMA. S split-bf16 (3 terms),
// P·V single fp16 term. smem 56KB.
// ===========================================================================
#define AQ_H 0
#define AQ_L 16384
#define AK_H 32768
#define AK_L 40960
#define AV_H 49152
#define ATT_SMEM 57344

__global__ __launch_bounds__(256, 1) void attn_tc()
{
    extern __shared__ unsigned char dynsm[];
    const uint32_t sb = smem_u32(dynsm);
    const int tid = threadIdx.x, lane = tid & 31, mw = tid >> 5;
    const int qt = 15 - (int)blockIdx.x;
    const int bh = blockIdx.y;
    const int q0 = qt * 128;
    const int b_off = ((lane >> 4) << 3) + (lane & 7);
    const int b_cb  = (lane >> 3) & 1;

    {
        const int row = tid >> 1, half = tid & 1;
        const size_t go = ((size_t)bh * Tn + q0 + row) * DHn + half * 32;
        const uint4* ph = (const uint4*)(g_qh + go);
        const uint4* pl = (const uint4*)(g_ql + go);
        #pragma unroll
        for (int c4 = 0; c4 < 4; c4++) {
            const uint32_t o = SWZA(row, half * 4 + c4);
            uint4 vh = ph[c4], vl = pl[c4];
            STS4(sb + AQ_H + o, vh.x, vh.y, vh.z, vh.w);
            STS4(sb + AQ_L + o, vl.x, vl.y, vl.z, vl.w);
        }
    }
    __syncthreads();

    uint32_t aQh[4][4], aQl[4][4];
    #pragma unroll
    for (int kc = 0; kc < 4; kc++) {
        const uint32_t o = SWZA(mw * 16 + (lane & 15), kc * 2 + (lane >> 4));
        LDSM4(aQh[kc], sb + AQ_H + o);
        LDSM4(aQl[kc], sb + AQ_L + o);
    }

    float co[8][4];
    #pragma unroll
    for (int i = 0; i < 8; i++)
        #pragma unroll
        for (int j = 0; j < 4; j++) co[i][j] = 0.f;
    float m0 = -1e30f, m1 = -1e30f, l0 = 0.f, l1 = 0.f;
    const int rowq = q0 + mw * 16 + (lane >> 2);
    const int nkt = 2 * qt + 2;

    for (int kt = 0; kt < nkt; kt++) {
        const int krow = tid >> 2, kq = tid & 3;
        const size_t go = ((size_t)bh * Tn + kt * 64 + krow) * DHn + kq * 16;
        uint4 vkh[2], vkl[2], vvh[2];
        { const uint4* p = (const uint4*)(g_kh + go); vkh[0]=p[0]; vkh[1]=p[1]; }
        { const uint4* p = (const uint4*)(g_kl + go); vkl[0]=p[0]; vkl[1]=p[1]; }
        { const uint4* p = (const uint4*)(g_vh + go); vvh[0]=p[0]; vvh[1]=p[1]; }
        __syncthreads();
        {
            const uint32_t o0 = SWZA(krow, kq * 2), o1 = SWZA(krow, kq * 2 + 1);
            STS4(sb + AK_H + o0, vkh[0].x, vkh[0].y, vkh[0].z, vkh[0].w);
            STS4(sb + AK_H + o1, vkh[1].x, vkh[1].y, vkh[1].z, vkh[1].w);
            STS4(sb + AK_L + o0, vkl[0].x, vkl[0].y, vkl[0].z, vkl[0].w);
            STS4(sb + AK_L + o1, vkl[1].x, vkl[1].y, vkl[1].z, vkl[1].w);
            STS4(sb + AV_H + o0, vvh[0].x, vvh[0].y, vvh[0].z, vvh[0].w);
            STS4(sb + AV_H + o1, vvh[1].x, vvh[1].y, vvh[1].z, vvh[1].w);
        }
        __syncthreads();

        float cs[8][4];
        #pragma unroll
        for (int i = 0; i < 8; i++)
            #pragma unroll
            for (int j = 0; j < 4; j++) cs[i][j] = 0.f;
        #pragma unroll
        for (int kc = 0; kc < 4; kc++) {
            uint32_t bKh[4][4], bKl[4][4];
            #pragma unroll
            for (int np = 0; np < 4; np++)
                LDSM4(bKh[np], sb + AK_H +
                      SWZA(np * 16 + b_off, kc * 2 + b_cb));
            #pragma unroll
            for (int nt = 0; nt < 8; nt++)
                MMA1(cs[nt], aQh[kc], bKh[nt>>1][(nt&1)*2],
                     bKh[nt>>1][(nt&1)*2+1]);
            #pragma unroll
            for (int nt = 0; nt < 8; nt++)
                MMA1(cs[nt], aQl[kc], bKh[nt>>1][(nt&1)*2],
                     bKh[nt>>1][(nt&1)*2+1]);
            #pragma unroll
            for (int np = 0; np < 4; np++)
                LDSM4(bKl[np], sb + AK_L +
                      SWZA(np * 16 + b_off, kc * 2 + b_cb));
            #pragma unroll
            for (int nt = 0; nt < 8; nt++)
                MMA1(cs[nt], aQh[kc], bKl[nt>>1][(nt&1)*2],
                     bKl[nt>>1][(nt&1)*2+1]);
        }

        const bool domask = (kt >= 2 * qt);
        float mt0 = -1e30f, mt1 = -1e30f;
        #pragma unroll
        for (int nt = 0; nt < 8; nt++) {
            const int ck = kt * 64 + nt * 8 + (lane & 3) * 2;
            float s0 = cs[nt][0] * 0.125f, s1 = cs[nt][1] * 0.125f;
            float s2 = cs[nt][2] * 0.125f, s3 = cs[nt][3] * 0.125f;
            if (domask) {
                if (ck     > rowq)     s0 = -1e30f;
                if (ck + 1 > rowq)     s1 = -1e30f;
                if (ck     > rowq + 8) s2 = -1e30f;
                if (ck + 1 > rowq + 8) s3 = -1e30f;
            }
            cs[nt][0] = s0; cs[nt][1] = s1; cs[nt][2] = s2; cs[nt][3] = s3;
            mt0 = fmaxf(mt0, fmaxf(s0, s1));
            mt1 = fmaxf(mt1, fmaxf(s2, s3));
        }
        mt0 = fmaxf(mt0, __shfl_xor_sync(0xffffffffu, mt0, 1));
        mt0 = fmaxf(mt0, __shfl_xor_sync(0xffffffffu, mt0, 2));
        mt1 = fmaxf(mt1, __shfl_xor_sync(0xffffffffu, mt1, 1));
        mt1 = fmaxf(mt1, __shfl_xor_sync(0xffffffffu, mt1, 2));
        const float nm0 = fmaxf(m0, mt0), nm1 = fmaxf(m1, mt1);
        const float cr0 = __expf(m0 - nm0), cr1 = __expf(m1 - nm1);
        m0 = nm0; m1 = nm1; l0 *= cr0; l1 *= cr1;

        uint32_t aP[4][4];
        #pragma unroll
        for (int nt = 0; nt < 8; nt++) {
            float p0 = __expf(cs[nt][0] - m0), p1 = __expf(cs[nt][1] - m0);
            float p2 = __expf(cs[nt][2] - m1), p3 = __expf(cs[nt][3] - m1);
            l0 += p0 + p1; l1 += p2 + p3;
            CVT_F16X2(aP[nt >> 1][(nt & 1) * 2],     p0, p1);
            CVT_F16X2(aP[nt >> 1][(nt & 1) * 2 + 1], p2, p3);
        }
        #pragma unroll
        for (int nt = 0; nt < 8; nt++) {
            co[nt][0] *= cr0; co[nt][1] *= cr0;
            co[nt][2] *= cr1; co[nt][3] *= cr1;
        }

        #pragma unroll
        for (int kc = 0; kc < 4; kc++) {
            uint32_t bVh[4][4];
            const uint32_t vrow = kc * 16 + ((lane >> 3) & 1) * 8 + (lane & 7);
            #pragma unroll
            for (int g = 0; g < 4; g++)
                LDSMT4(bVh[g], sb + AV_H + SWZA(vrow, 2 * g + (lane >> 4)));
            #pragma unroll
            for (int nt = 0; nt < 8; nt++)
                MMA1H(co[nt], aP[kc], bVh[nt>>1][(nt&1)*2],
                      bVh[nt>>1][(nt&1)*2+1]);
        }
    }

    l0 += __shfl_xor_sync(0xffffffffu, l0, 1);
    l0 += __shfl_xor_sync(0xffffffffu, l0, 2);
    l1 += __shfl_xor_sync(0xffffffffu, l1, 1);
    l1 += __shfl_xor_sync(0xffffffffu, l1, 2);
    const float i0 = 1.f / l0, i1 = 1.f / l1;
    const int b = bh / Hn, h = bh % Hn;
    const int t0 = q0 + mw * 16 + (lane >> 2);
    const size_t base0 = (size_t)(b * Tn + t0)     * DMn + h * DHn;
    const size_t base1 = (size_t)(b * Tn + t0 + 8) * DMn + h * DHn;
    #pragma unroll
    for (int nt = 0; nt < 8; nt++) {
        const int dh = nt * 8 + (lane & 3) * 2;
        uint32_t hh, ll;
        packhl(co[nt][0] * i0, co[nt][1] * i0, hh, ll);
        *(uint32_t*)(g_oh + base0 + dh) = hh;
        *(uint32_t*)(g_ol + base0 + dh) = ll;
        packhl(co[nt][2] * i1, co[nt][3] * i1, hh, ll);
        *(uint32_t*)(g_oh + base1 + dh) = hh;
        *(uint32_t*)(g_ol + base1 + dh) = ll;
    }
}

// ---------------------------------------------------------------------------
extern "C" void kernel_launch(void* const* d_in, const int* in_sizes, int n_in,
                              void* d_out, int out_size)
{
    const float* x    = (const float*)d_in[0];
    const float* cosb = (const float*)d_in[1];
    const float* sinb = (const float*)d_in[2];
    const float* wq   = (const float*)d_in[3];
    const float* wk   = (const float*)d_in[4];
    const float* wv   = (const float*)d_in[5];
    const float* wo   = (const float*)d_in[6];
    float* out = (float*)d_out;

    cudaFuncSetAttribute(qkv_tc,
        cudaFuncAttributeMaxDynamicSharedMemorySize, NSTAGE * BUFSZ);
    cudaFuncSetAttribute(proj_tc,
        cudaFuncAttributeMaxDynamicSharedMemorySize, NSTAGE * BUFSZ);
    cudaFuncSetAttribute(attn_tc,
        cudaFuncAttributeMaxDynamicSharedMemorySize, ATT_SMEM);

    const int total4 = X4 + 4 * W4;
    split_all<<<(total4 + 255) / 256, 256>>>(x, wq, wk, wv, wo);

    dim3 gA(36, 64);
    qkv_tc<<<gA, 256, NSTAGE * BUFSZ>>>(cosb, sinb);

    dim3 gB(16, 48);
    attn_tc<<<gB, 256, ATT_SMEM>>>();

    dim3 gC(12, 64);
    proj_tc<<<gC, 256, NSTAGE * BUFSZ>>>(out);
}